// round 12
// baseline (speedup 1.0000x reference)
#include <cuda_runtime.h>
#include <cuda_bf16.h>
#include <math.h>
#include <stdint.h>
#include <stddef.h>

#define BB 64
#define NN 8192
#define MODES 16
#define J2 32
#define NT 128
#define TBC (NN / NT)

typedef __nv_bfloat16 bf16;

// ---------------- device scratch --------------------------------------------
__device__ bf16  g_hH0[(size_t)BB * NN * 64];
__device__ bf16  g_hL0[(size_t)BB * NN * 64];
__device__ bf16  g_hH1[(size_t)BB * NN * 64];
__device__ bf16  g_hL1[(size_t)BB * NN * 64];
__device__ float g_pF[(size_t)BB * TBC * J2 * 64];    // [b][chunk][j][c]
__device__ float g_F[(size_t)BB * J2 * 64];           // [b][j][c]
__device__ bf16  g_basDH[(size_t)J2 * NN];            // [j][n] hi
__device__ bf16  g_basDL[(size_t)J2 * NN];            // [j][n] lo
__device__ bf16  g_cwH[4 * 64 * 64];                  // [l][o][c]
__device__ bf16  g_cwL[4 * 64 * 64];
__device__ bf16  g_GpP[(size_t)BB * 64 * 64];         // [b][o][ gh(32) | gl(32) ]
__device__ bf16  g_w1TH[128 * 64];                    // [j][c]
__device__ bf16  g_w1TL[128 * 64];

// ---------------- helpers ----------------------------------------------------
#define SWZ(x) ((x) ^ (((x) >> 3) & 0x70))

__device__ __forceinline__ uint32_t smem_u32(const void* p) {
    uint32_t a;
    asm("{ .reg .u64 t; cvta.to.shared.u64 t, %1; cvt.u32.u64 %0, t; }" : "=r"(a) : "l"(p));
    return a;
}
__device__ __forceinline__ void cpa16(uint32_t dst, const void* src) {
    asm volatile("cp.async.cg.shared.global [%0], [%1], 16;" :: "r"(dst), "l"(src));
}
#define CPA_COMMIT() asm volatile("cp.async.commit_group;" ::: "memory")
#define CPA_WAIT(n)  asm volatile("cp.async.wait_group %0;" :: "n"(n) : "memory")

__device__ __forceinline__ void ldsm4(uint32_t a, uint32_t* r) {
    asm volatile("ldmatrix.sync.aligned.m8n8.x4.shared.b16 {%0,%1,%2,%3}, [%4];"
                 : "=r"(r[0]), "=r"(r[1]), "=r"(r[2]), "=r"(r[3]) : "r"(a));
}
__device__ __forceinline__ void ldsm4t(uint32_t a, uint32_t* r) {
    asm volatile("ldmatrix.sync.aligned.m8n8.x4.trans.shared.b16 {%0,%1,%2,%3}, [%4];"
                 : "=r"(r[0]), "=r"(r[1]), "=r"(r[2]), "=r"(r[3]) : "r"(a));
}
__device__ __forceinline__ void mma16816(float* d, const uint32_t* a, const uint32_t* b) {
    asm volatile(
        "mma.sync.aligned.m16n8k16.row.col.f32.bf16.bf16.f32 "
        "{%0,%1,%2,%3},{%4,%5,%6,%7},{%8,%9},{%0,%1,%2,%3};"
        : "+f"(d[0]), "+f"(d[1]), "+f"(d[2]), "+f"(d[3])
        : "r"(a[0]), "r"(a[1]), "r"(a[2]), "r"(a[3]), "r"(b[0]), "r"(b[1]));
}
__device__ __forceinline__ float gelu_exact(float v) {
    return 0.5f * v * (1.0f + erff(v * 0.70710678118654752f));
}
__device__ __forceinline__ void split_bf(float v, bf16& h, bf16& l) {
    h = __float2bfloat16(v);
    l = __float2bfloat16(v - __bfloat162float(h));
}
__device__ __forceinline__ uint32_t pack_bf(bf16 a, bf16 b) {
    return (uint32_t)__bfloat16_as_ushort(a) | ((uint32_t)__bfloat16_as_ushort(b) << 16);
}

// ---------------- merged prep (one launch) -----------------------------------
// grid.x 0..NN/256-1: basis rows; then weight blocks appended.
__global__ void prep_all(const float* __restrict__ cw, const float* __restrict__ w1) {
    int gidx = blockIdx.x * 256 + threadIdx.x;
    if (gidx < NN) {
        int n = gidx;
#pragma unroll
        for (int m = 0; m < MODES; m++) {
            int r = (m * n) & (NN - 1);
            float tf = 2.0f * (float)r / (float)NN;
            float s, c;
            sincospif(tf, &s, &c);
            bf16 h, l;
            split_bf(c, h, l);
            g_basDH[(size_t)(2 * m) * NN + n] = h;
            g_basDL[(size_t)(2 * m) * NN + n] = l;
            split_bf(s, h, l);
            g_basDH[(size_t)(2 * m + 1) * NN + n] = h;
            g_basDL[(size_t)(2 * m + 1) * NN + n] = l;
        }
    } else if (gidx < NN + 4 * 64 * 64) {
        int idx = gidx - NN;
        bf16 h, l;
        split_bf(cw[idx], h, l);
        g_cwH[idx] = h; g_cwL[idx] = l;
    } else if (gidx < NN + 4 * 64 * 64 + 128 * 64) {
        int i2 = gidx - NN - 4 * 64 * 64;
        int c = i2 >> 7, j = i2 & 127;
        bf16 h, l;
        split_bf(w1[c * 128 + j], h, l);
        g_w1TH[j * 64 + c] = h; g_w1TL[j * 64 + c] = l;
    }
}

// ---------------- DFT MMA core (8 warps) -------------------------------------
__device__ __forceinline__ void dft_core8(uint32_t sb, int VHo, int VLo, int BHo, int BLo,
                                          int wid, int lane, size_t pfbase) {
    int lr = lane & 7, li = lane >> 3;
    int drA = (li & 1) * 8, dcA = (li >> 1) * 16;
    int jt = (wid & 1) * 16;
    int cb2 = (wid >> 1) * 32;
    float f[2][4];
#pragma unroll
    for (int i = 0; i < 2; i++)
#pragma unroll
        for (int k = 0; k < 4; k++) f[i][k] = 0.0f;

#pragma unroll
    for (int s = 0; s < 8; s++) {
        int half = s >> 2, kb = (s & 3) * 32;
        uint32_t ah[4], al[4], bh[4], bl[4];
        ldsm4(sb + BHo + half * 4096 + SWZ((jt + drA + lr) * 128 + kb + dcA), ah);
        ldsm4(sb + BLo + half * 4096 + SWZ((jt + drA + lr) * 128 + kb + dcA), al);
        ldsm4t(sb + VHo + SWZ((16 * s + drA + lr) * 128 + cb2 + dcA), bh);
        ldsm4t(sb + VLo + SWZ((16 * s + drA + lr) * 128 + cb2 + dcA), bl);
        mma16816(f[0], ah, bh); mma16816(f[1], ah, bh + 2);
        mma16816(f[0], al, bh); mma16816(f[1], al, bh + 2);
        mma16816(f[0], ah, bl); mma16816(f[1], ah, bl + 2);
    }
    int q = lane & 3, g = lane >> 2;
    int cbase = (wid >> 1) * 16;
#pragma unroll
    for (int i = 0; i < 2; i++) {
        int c = cbase + i * 8 + 2 * q;
        int j = jt + g;
        *(float2*)&g_pF[(pfbase + j) * 64 + c]     = make_float2(f[i][0], f[i][1]);
        *(float2*)&g_pF[(pfbase + j + 8) * 64 + c] = make_float2(f[i][2], f[i][3]);
    }
}

// ---------------- fused fc0 + DFT --------------------------------------------
#define F0_VH 0
#define F0_VL 16384
#define F0_BH 32768
#define F0_BL 40960
#define F0_W0 49152
#define F0_SZ 50176

__global__ __launch_bounds__(256, 3)
void fc0dft_kernel(const float* __restrict__ xg, const float* __restrict__ tg,
                   const float* __restrict__ w0, const float* __restrict__ b0) {
    extern __shared__ char smc[];
    uint32_t sb = smem_u32(smc);
    float* w0s = (float*)(smc + F0_W0);
    float* b0s = w0s + 128;
    int tid = threadIdx.x, wid = tid >> 5, lane = tid & 31;
    int b = blockIdx.y, n0 = blockIdx.x * NT;

    for (int i = tid; i < 512; i += 256) {
        int half = i >> 8, rest = i & 255, j = rest >> 3, q = rest & 7;
        uint32_t so = half * 4096 + SWZ(j * 128 + q * 16);
        cpa16(sb + F0_BH + so, (const uint4*)(g_basDH + (size_t)j * NN + n0 + half * 64) + q);
        cpa16(sb + F0_BL + so, (const uint4*)(g_basDL + (size_t)j * NN + n0 + half * 64) + q);
    }
    CPA_COMMIT();
    if (tid < 128) w0s[tid] = w0[tid];
    if (tid < 64)  b0s[tid] = b0[tid];
    __syncthreads();

    int n = tid >> 1, c0 = (tid & 1) * 32;
    float xv = xg[(size_t)b * NN + n0 + n], tv = tg[(size_t)b * NN + n0 + n];
    uint32_t hw[16], lw[16];
#pragma unroll
    for (int k = 0; k < 16; k++) {
        int c = c0 + 2 * k;
        float v0 = fmaf(w0s[c],     xv, fmaf(w0s[64 + c],     tv, b0s[c]));
        float v1 = fmaf(w0s[c + 1], xv, fmaf(w0s[64 + c + 1], tv, b0s[c + 1]));
        bf16 h0, l0, h1, l1;
        split_bf(v0, h0, l0);
        split_bf(v1, h1, l1);
        hw[k] = pack_bf(h0, h1);
        lw[k] = pack_bf(l0, l1);
    }
    size_t ro = ((size_t)b * NN + n0 + n) * 64 + c0;
#pragma unroll
    for (int g4 = 0; g4 < 4; g4++) {
        uint4 hv = make_uint4(hw[4 * g4], hw[4 * g4 + 1], hw[4 * g4 + 2], hw[4 * g4 + 3]);
        uint4 lv = make_uint4(lw[4 * g4], lw[4 * g4 + 1], lw[4 * g4 + 2], lw[4 * g4 + 3]);
        *(uint4*)(g_hH0 + ro + 8 * g4) = hv;
        *(uint4*)(g_hL0 + ro + 8 * g4) = lv;
        uint32_t so = SWZ(n * 128 + c0 * 2 + g4 * 16);
        *(uint4*)(smc + F0_VH + so) = hv;
        *(uint4*)(smc + F0_VL + so) = lv;
    }
    CPA_WAIT(0);
    __syncthreads();
    dft_core8(sb, F0_VH, F0_VL, F0_BH, F0_BL, wid, lane,
              ((size_t)b * TBC + blockIdx.x) * J2);
}

// ---------------- reduce (wide grid, float4) + modemix -----------------------
__global__ __launch_bounds__(128)
void reduce_kernel() {
    int b = blockIdx.x;
    int idx = (blockIdx.y * 128 + threadIdx.x) * 4;
    const float4* p = (const float4*)&g_pF[(size_t)b * TBC * 2048 + idx];
    float4 s = make_float4(0.f, 0.f, 0.f, 0.f);
#pragma unroll 8
    for (int ch = 0; ch < TBC; ch++) {
        float4 v = p[(size_t)ch * 512];
        s.x += v.x; s.y += v.y; s.z += v.z; s.w += v.w;
    }
    *(float4*)&g_F[(size_t)b * 2048 + idx] = s;
}

__global__ __launch_bounds__(1024)
void modemix_kernel(const float* __restrict__ swr,
                    const float* __restrict__ swi) {
    __shared__ float fs[64 * 33];   // [c][j]
    int b = blockIdx.x, tid = threadIdx.x;
    for (int idx = tid; idx < 2048; idx += 1024) {
        int j = idx >> 6, c = idx & 63;
        fs[c * 33 + j] = g_F[(size_t)b * 2048 + idx];
    }
    __syncthreads();
    int m = tid & 15, o = tid >> 4;
    float re = 0.0f, im = 0.0f;
    for (int i = 0; i < 64; i++) {
        float fr = fs[i * 33 + 2 * m];
        float fn = fs[i * 33 + 2 * m + 1];
        float wr = swr[(i * 64 + o) * 16 + m];
        float wi = swi[(i * 64 + o) * 16 + m];
        re = fmaf(fr, wr, fmaf(fn, wi, re));
        im = fmaf(fr, wi, fmaf(-fn, wr, im));
    }
    float cm = (m == 0 ? 1.0f : 2.0f) / (float)NN;
    float g0 = cm * re;
    float g1 = -cm * im;
    size_t r = ((size_t)b * 64 + o) * 64;
    bf16 h, l;
    split_bf(g0, h, l);
    g_GpP[r + 2 * m] = h;      g_GpP[r + 32 + 2 * m] = l;
    split_bf(g1, h, l);
    g_GpP[r + 2 * m + 1] = h;  g_GpP[r + 32 + 2 * m + 1] = l;
}

// ---------------- fused layer: conv + synthesis (+gelu) (+DFT) ----------------
#define MM_HH  0
#define MM_HL  16384
#define MM_WH  32768
#define MM_WL  40960
#define MM_BDH 49152
#define MM_BDL 57344
#define MM_G   65536
#define MM_CB  73728
#define MM_SZ  73984

template <bool GELU, bool DFT>
__global__ __launch_bounds__(256, 3)
void mma_layer(int dir, int layer, int rev, const float* __restrict__ cb_all) {
    extern __shared__ char smc[];
    uint32_t sb = smem_u32(smc);
    int tid = threadIdx.x, wid = tid >> 5, lane = tid & 31;
    int b   = rev ? (BB - 1 - (int)blockIdx.y) : (int)blockIdx.y;
    int chk = rev ? (TBC - 1 - (int)blockIdx.x) : (int)blockIdx.x;
    int n0 = chk * NT;

    const bf16* hHsrc = (dir ? g_hH1 : g_hH0) + ((size_t)b * NN + n0) * 64;
    const bf16* hLsrc = (dir ? g_hL1 : g_hL0) + ((size_t)b * NN + n0) * 64;
    bf16* hHdst = (dir ? g_hH0 : g_hH1) + ((size_t)b * NN + n0) * 64;
    bf16* hLdst = (dir ? g_hL0 : g_hL1) + ((size_t)b * NN + n0) * 64;

    // ---- group A: h tiles + conv weights ------------------------------------
    for (int i = tid; i < 1024; i += 256) {
        int r = i >> 3, q = i & 7;
        uint32_t so = SWZ(r * 128 + q * 16);
        cpa16(sb + MM_HH + so, (const uint4*)(hHsrc + (size_t)r * 64) + q);
        cpa16(sb + MM_HL + so, (const uint4*)(hLsrc + (size_t)r * 64) + q);
    }
    for (int i = tid; i < 512; i += 256) {
        int r = i >> 3, q = i & 7;
        uint32_t so = SWZ(r * 128 + q * 16);
        cpa16(sb + MM_WH + so, (const uint4*)(g_cwH + (size_t)(layer * 64 + r) * 64) + q);
        cpa16(sb + MM_WL + so, (const uint4*)(g_cwL + (size_t)(layer * 64 + r) * 64) + q);
    }
    CPA_COMMIT();
    // ---- group B: G + DFT basis ---------------------------------------------
    for (int i = tid; i < 512; i += 256) {
        int r = i >> 3, q = i & 7;
        uint32_t so = SWZ(r * 128 + q * 16);
        cpa16(sb + MM_G + so, (const uint4*)(g_GpP + ((size_t)b * 64 + r) * 64) + q);
        int half = i >> 8, rest = i & 255, j = rest >> 3, qq = rest & 7;
        uint32_t so2 = half * 4096 + SWZ(j * 128 + qq * 16);
        cpa16(sb + MM_BDH + so2, (const uint4*)(g_basDH + (size_t)j * NN + n0 + half * 64) + qq);
        cpa16(sb + MM_BDL + so2, (const uint4*)(g_basDL + (size_t)j * NN + n0 + half * 64) + qq);
    }
    CPA_COMMIT();
    if (tid < 64) ((float*)(smc + MM_CB))[tid] = cb_all[layer * 64 + tid];
    CPA_WAIT(1);
    __syncthreads();

    int lr = lane & 7, li = lane >> 3;
    int drA = (li & 1) * 8, dcA = (li >> 1) * 16;
    int drB = (li >> 1) * 8, dcB = (li & 1) * 16;
    int rA0 = 16 * wid;

    float acc[8][4];
#pragma unroll
    for (int nt = 0; nt < 8; nt++)
#pragma unroll
        for (int k = 0; k < 4; k++) acc[nt][k] = 0.0f;

    // conv: (Hh+Hl)(Wh+Wl) 3-term — overlaps group B flight
#pragma unroll
    for (int s = 0; s < 4; s++) {
        int kb = s * 32;
        uint32_t ah[4], al[4];
        ldsm4(sb + MM_HH + SWZ((rA0 + drA + lr) * 128 + kb + dcA), ah);
        ldsm4(sb + MM_HL + SWZ((rA0 + drA + lr) * 128 + kb + dcA), al);
#pragma unroll
        for (int np = 0; np < 4; np++) {
            uint32_t bb[4];
            ldsm4(sb + MM_WH + SWZ((np * 16 + drB + lr) * 128 + kb + dcB), bb);
            mma16816(acc[2 * np],     ah, bb);
            mma16816(acc[2 * np + 1], ah, bb + 2);
            mma16816(acc[2 * np],     al, bb);
            mma16816(acc[2 * np + 1], al, bb + 2);
            ldsm4(sb + MM_WL + SWZ((np * 16 + drB + lr) * 128 + kb + dcB), bb);
            mma16816(acc[2 * np],     ah, bb);
            mma16816(acc[2 * np + 1], ah, bb + 2);
        }
    }
    CPA_WAIT(0);
    __syncthreads();

    // synthesis: A = trans(basD half tile), B = packed G
    {
        int halfS = rA0 >> 6;
        int colA = (rA0 & 63) * 2 + (li & 1) * 16;
        int rowA = (li >> 1) * 8 + lr;
#pragma unroll
        for (int s = 0; s < 2; s++) {
            int kb = s * 32;
            uint32_t ah[4], al[4];
            ldsm4t(sb + MM_BDH + halfS * 4096 + SWZ((s * 16 + rowA) * 128 + colA), ah);
            ldsm4t(sb + MM_BDL + halfS * 4096 + SWZ((s * 16 + rowA) * 128 + colA), al);
#pragma unroll
            for (int np = 0; np < 4; np++) {
                uint32_t bb[4];
                ldsm4(sb + MM_G + SWZ((np * 16 + drB + lr) * 128 + kb + dcB), bb);
                mma16816(acc[2 * np],     ah, bb);
                mma16816(acc[2 * np + 1], ah, bb + 2);
                mma16816(acc[2 * np],     al, bb);
                mma16816(acc[2 * np + 1], al, bb + 2);
                ldsm4(sb + MM_G + SWZ((np * 16 + drB + lr) * 128 + 64 + kb + dcB), bb);
                mma16816(acc[2 * np],     ah, bb);
                mma16816(acc[2 * np + 1], ah, bb + 2);
            }
        }
    }
    __syncthreads();

    // epilogue: bias + gelu, write vH/vL into HH/HL
    int q = lane & 3, g = lane >> 2;
    const float* cbs = (const float*)(smc + MM_CB);
#pragma unroll
    for (int nt = 0; nt < 8; nt++) {
        int o0 = nt * 8 + 2 * q;
        int r0 = 16 * wid + g;
        float v0 = acc[nt][0] + cbs[o0];
        float v1 = acc[nt][1] + cbs[o0 + 1];
        float v2 = acc[nt][2] + cbs[o0];
        float v3 = acc[nt][3] + cbs[o0 + 1];
        if (GELU) {
            v0 = gelu_exact(v0); v1 = gelu_exact(v1);
            v2 = gelu_exact(v2); v3 = gelu_exact(v3);
        }
        bf16 h0, l0, h1, l1;
        split_bf(v0, h0, l0); split_bf(v1, h1, l1);
        *(uint32_t*)(smc + MM_HH + SWZ(r0 * 128 + o0 * 2)) = pack_bf(h0, h1);
        *(uint32_t*)(smc + MM_HL + SWZ(r0 * 128 + o0 * 2)) = pack_bf(l0, l1);
        split_bf(v2, h0, l0); split_bf(v3, h1, l1);
        *(uint32_t*)(smc + MM_HH + SWZ((r0 + 8) * 128 + o0 * 2)) = pack_bf(h0, h1);
        *(uint32_t*)(smc + MM_HL + SWZ((r0 + 8) * 128 + o0 * 2)) = pack_bf(l0, l1);
    }
    __syncthreads();

    for (int i = tid; i < 1024; i += 256) {
        int r = i >> 3, qq = i & 7;
        uint32_t so = SWZ(r * 128 + qq * 16);
        ((uint4*)(hHdst + (size_t)r * 64))[qq] = *(uint4*)(smc + MM_HH + so);
        ((uint4*)(hLdst + (size_t)r * 64))[qq] = *(uint4*)(smc + MM_HL + so);
    }
    if (DFT) {
        dft_core8(sb, MM_HH, MM_HL, MM_BDH, MM_BDL, wid, lane,
                  ((size_t)b * TBC + chk) * J2);
    }
}

// ---------------- fc1 + gelu + fc2 via MMA -----------------------------------
#define FC_HH 0
#define FC_HL 16384
#define FC_WH 32768
#define FC_WL 49152
#define FC_B1 65536
#define FC_W2 66048
#define FC_SZ 66560

__global__ __launch_bounds__(256, 3)
void fc12_kernel(const float* __restrict__ b1, const float* __restrict__ w2,
                 const float* __restrict__ b2, float* __restrict__ out) {
    extern __shared__ char smc[];
    uint32_t sb = smem_u32(smc);
    int tid = threadIdx.x, wid = tid >> 5, lane = tid & 31;
    int b = BB - 1 - (int)blockIdx.y;
    int n0 = (TBC - 1 - (int)blockIdx.x) * NT;

    const bf16* hH = g_hH0 + ((size_t)b * NN + n0) * 64;
    const bf16* hL = g_hL0 + ((size_t)b * NN + n0) * 64;
    for (int i = tid; i < 1024; i += 256) {
        int r = i >> 3, q = i & 7;
        uint32_t so = SWZ(r * 128 + q * 16);
        cpa16(sb + FC_HH + so, (const uint4*)(hH + (size_t)r * 64) + q);
        cpa16(sb + FC_HL + so, (const uint4*)(hL + (size_t)r * 64) + q);
        cpa16(sb + FC_WH + so, (const uint4*)(g_w1TH + (size_t)r * 64) + q);
        cpa16(sb + FC_WL + so, (const uint4*)(g_w1TL + (size_t)r * 64) + q);
    }
    CPA_COMMIT();
    if (tid < 128) {
        ((float*)(smc + FC_B1))[tid] = b1[tid];
        ((float*)(smc + FC_W2))[tid] = w2[tid];
    }
    CPA_WAIT(0);
    __syncthreads();

    int lr = lane & 7, li = lane >> 3;
    int drA = (li & 1) * 8, dcA = (li >> 1) * 16;
    int drB = (li >> 1) * 8, dcB = (li & 1) * 16;
    int rA0 = 16 * wid;

    float acc[16][4];
#pragma unroll
    for (int nt = 0; nt < 16; nt++)
#pragma unroll
        for (int k = 0; k < 4; k++) acc[nt][k] = 0.0f;

#pragma unroll
    for (int s = 0; s < 4; s++) {
        int kb = s * 32;
        uint32_t ah[4], al[4];
        ldsm4(sb + FC_HH + SWZ((rA0 + drA + lr) * 128 + kb + dcA), ah);
        ldsm4(sb + FC_HL + SWZ((rA0 + drA + lr) * 128 + kb + dcA), al);
#pragma unroll
        for (int np = 0; np < 8; np++) {
            uint32_t bb[4];
            ldsm4(sb + FC_WH + SWZ((np * 16 + drB + lr) * 128 + kb + dcB), bb);
            mma16816(acc[2 * np],     ah, bb);
            mma16816(acc[2 * np + 1], ah, bb + 2);
            mma16816(acc[2 * np],     al, bb);
            mma16816(acc[2 * np + 1], al, bb + 2);
            ldsm4(sb + FC_WL + SWZ((np * 16 + drB + lr) * 128 + kb + dcB), bb);
            mma16816(acc[2 * np],     ah, bb);
            mma16816(acc[2 * np + 1], ah, bb + 2);
        }
    }

    int q = lane & 3, g = lane >> 2;
    const float* b1s = (const float*)(smc + FC_B1);
    const float* w2s = (const float*)(smc + FC_W2);
    float s0 = 0.0f, s1 = 0.0f;
#pragma unroll
    for (int nt = 0; nt < 16; nt++) {
        int j0 = nt * 8 + 2 * q;
        s0 = fmaf(w2s[j0],     gelu_exact(acc[nt][0] + b1s[j0]),     s0);
        s0 = fmaf(w2s[j0 + 1], gelu_exact(acc[nt][1] + b1s[j0 + 1]), s0);
        s1 = fmaf(w2s[j0],     gelu_exact(acc[nt][2] + b1s[j0]),     s1);
        s1 = fmaf(w2s[j0 + 1], gelu_exact(acc[nt][3] + b1s[j0 + 1]), s1);
    }
    s0 += __shfl_xor_sync(0xffffffffu, s0, 1);
    s0 += __shfl_xor_sync(0xffffffffu, s0, 2);
    s1 += __shfl_xor_sync(0xffffffffu, s1, 1);
    s1 += __shfl_xor_sync(0xffffffffu, s1, 2);
    if (q == 0) {
        float bv = b2[0];
        out[(size_t)b * NN + n0 + 16 * wid + g]     = s0 + bv;
        out[(size_t)b * NN + n0 + 16 * wid + g + 8] = s1 + bv;
    }
}

// ---------------- host launcher ----------------------------------------------
extern "C" void kernel_launch(void* const* d_in, const int* in_sizes, int n_in,
                              void* d_out, int out_size) {
    const float* x    = (const float*)d_in[0];
    const float* t    = (const float*)d_in[1];
    const float* fc0w = (const float*)d_in[2];
    const float* fc0b = (const float*)d_in[3];
    const float* swr  = (const float*)d_in[4];
    const float* swi  = (const float*)d_in[5];
    const float* cw   = (const float*)d_in[6];
    const float* cb   = (const float*)d_in[7];
    const float* w1   = (const float*)d_in[8];
    const float* b1   = (const float*)d_in[9];
    const float* w2   = (const float*)d_in[10];
    const float* b2   = (const float*)d_in[11];
    float* out = (float*)d_out;

    cudaFuncSetAttribute(mma_layer<true,  true >, cudaFuncAttributeMaxDynamicSharedMemorySize, MM_SZ);
    cudaFuncSetAttribute(mma_layer<false, false>, cudaFuncAttributeMaxDynamicSharedMemorySize, MM_SZ);
    cudaFuncSetAttribute(fc0dft_kernel, cudaFuncAttributeMaxDynamicSharedMemorySize, F0_SZ);
    cudaFuncSetAttribute(fc12_kernel, cudaFuncAttributeMaxDynamicSharedMemorySize, FC_SZ);

    dim3 g(TBC, BB);
    dim3 gr(BB, 4);   // 128 thr x float4: 4*128*4 = 2048 elems per b
    // launch order puts mma_layer at ncu's sampled launch (#5):
    // 1 prep_all, 2 fc0dft, 3 reduce, 4 modemix, 5 mma_layer, ...
    prep_all<<<(NN + 4 * 4096 + 128 * 64 + 255) / 256, 256>>>(cw, w1);

    fc0dft_kernel<<<g, 256, F0_SZ>>>(x, t, fc0w, fc0b);   // forward

    const size_t SWL = (size_t)64 * 64 * 16;
    reduce_kernel<<<gr, 128>>>();
    modemix_kernel<<<BB, 1024>>>(swr + 0 * SWL, swi + 0 * SWL);
    mma_layer<true, true><<<g, 256, MM_SZ>>>(0, 0, 1, cb);   // reversed

    reduce_kernel<<<gr, 128>>>();
    modemix_kernel<<<BB, 1024>>>(swr + 1 * SWL, swi + 1 * SWL);
    mma_layer<true, true><<<g, 256, MM_SZ>>>(1, 1, 0, cb);   // forward

    reduce_kernel<<<gr, 128>>>();
    modemix_kernel<<<BB, 1024>>>(swr + 2 * SWL, swi + 2 * SWL);
    mma_layer<true, true><<<g, 256, MM_SZ>>>(0, 2, 1, cb);   // reversed

    reduce_kernel<<<gr, 128>>>();
    modemix_kernel<<<BB, 1024>>>(swr + 3 * SWL, swi + 3 * SWL);
    mma_layer<false, false><<<g, 256, MM_SZ>>>(1, 3, 0, cb); // forward

    fc12_kernel<<<g, 256, FC_SZ>>>(b1, w2, b2, out);         // reversed
}

// round 13
// speedup vs baseline: 1.0791x; 1.0791x over previous
#include <cuda_runtime.h>
#include <cuda_bf16.h>
#include <math.h>
#include <stdint.h>
#include <stddef.h>

#define BB 64
#define NN 8192
#define MODES 16
#define J2 32
#define NT 128
#define TBC (NN / NT)

typedef __nv_bfloat16 bf16;

// ---------------- device scratch --------------------------------------------
__device__ bf16  g_hH0[(size_t)BB * NN * 64];
__device__ bf16  g_hL0[(size_t)BB * NN * 64];
__device__ bf16  g_hH1[(size_t)BB * NN * 64];
__device__ bf16  g_hL1[(size_t)BB * NN * 64];
__device__ float g_pF[(size_t)BB * TBC * J2 * 64];    // [b][chunk][j][c]
__device__ float g_F[(size_t)BB * J2 * 64];           // [b][j][c]
__device__ bf16  g_basDH[(size_t)J2 * NN];            // [j][n] hi
__device__ bf16  g_basDL[(size_t)J2 * NN];            // [j][n] lo
__device__ bf16  g_cwH[4 * 64 * 64];                  // [l][o][c]
__device__ bf16  g_cwL[4 * 64 * 64];
__device__ bf16  g_GpP[(size_t)BB * 64 * 64];         // [b][o][ gh(32) | gl(32) ]
__device__ bf16  g_w1TH[128 * 64];                    // [j][c]
__device__ bf16  g_w1TL[128 * 64];

// ---------------- helpers ----------------------------------------------------
#define SWZ(x) ((x) ^ (((x) >> 3) & 0x70))

__device__ __forceinline__ uint32_t smem_u32(const void* p) {
    uint32_t a;
    asm("{ .reg .u64 t; cvta.to.shared.u64 t, %1; cvt.u32.u64 %0, t; }" : "=r"(a) : "l"(p));
    return a;
}
__device__ __forceinline__ void cpa16(uint32_t dst, const void* src) {
    asm volatile("cp.async.cg.shared.global [%0], [%1], 16;" :: "r"(dst), "l"(src));
}
#define CPA_COMMIT() asm volatile("cp.async.commit_group;" ::: "memory")
#define CPA_WAIT(n)  asm volatile("cp.async.wait_group %0;" :: "n"(n) : "memory")

__device__ __forceinline__ void ldsm4(uint32_t a, uint32_t* r) {
    asm volatile("ldmatrix.sync.aligned.m8n8.x4.shared.b16 {%0,%1,%2,%3}, [%4];"
                 : "=r"(r[0]), "=r"(r[1]), "=r"(r[2]), "=r"(r[3]) : "r"(a));
}
__device__ __forceinline__ void ldsm4t(uint32_t a, uint32_t* r) {
    asm volatile("ldmatrix.sync.aligned.m8n8.x4.trans.shared.b16 {%0,%1,%2,%3}, [%4];"
                 : "=r"(r[0]), "=r"(r[1]), "=r"(r[2]), "=r"(r[3]) : "r"(a));
}
__device__ __forceinline__ void mma16816(float* d, const uint32_t* a, const uint32_t* b) {
    asm volatile(
        "mma.sync.aligned.m16n8k16.row.col.f32.bf16.bf16.f32 "
        "{%0,%1,%2,%3},{%4,%5,%6,%7},{%8,%9},{%0,%1,%2,%3};"
        : "+f"(d[0]), "+f"(d[1]), "+f"(d[2]), "+f"(d[3])
        : "r"(a[0]), "r"(a[1]), "r"(a[2]), "r"(a[3]), "r"(b[0]), "r"(b[1]));
}
__device__ __forceinline__ float gelu_exact(float v) {
    return 0.5f * v * (1.0f + erff(v * 0.70710678118654752f));
}
__device__ __forceinline__ void split_bf(float v, bf16& h, bf16& l) {
    h = __float2bfloat16(v);
    l = __float2bfloat16(v - __bfloat162float(h));
}
__device__ __forceinline__ uint32_t pack_bf(bf16 a, bf16 b) {
    return (uint32_t)__bfloat16_as_ushort(a) | ((uint32_t)__bfloat16_as_ushort(b) << 16);
}

// ---------------- merged prep (one launch) -----------------------------------
__global__ void prep_all(const float* __restrict__ cw, const float* __restrict__ w1) {
    int gidx = blockIdx.x * 256 + threadIdx.x;
    if (gidx < NN) {
        int n = gidx;
#pragma unroll
        for (int m = 0; m < MODES; m++) {
            int r = (m * n) & (NN - 1);
            float tf = 2.0f * (float)r / (float)NN;
            float s, c;
            sincospif(tf, &s, &c);
            bf16 h, l;
            split_bf(c, h, l);
            g_basDH[(size_t)(2 * m) * NN + n] = h;
            g_basDL[(size_t)(2 * m) * NN + n] = l;
            split_bf(s, h, l);
            g_basDH[(size_t)(2 * m + 1) * NN + n] = h;
            g_basDL[(size_t)(2 * m + 1) * NN + n] = l;
        }
    } else if (gidx < NN + 4 * 64 * 64) {
        int idx = gidx - NN;
        bf16 h, l;
        split_bf(cw[idx], h, l);
        g_cwH[idx] = h; g_cwL[idx] = l;
    } else if (gidx < NN + 4 * 64 * 64 + 128 * 64) {
        int i2 = gidx - NN - 4 * 64 * 64;
        int c = i2 >> 7, j = i2 & 127;
        bf16 h, l;
        split_bf(w1[c * 128 + j], h, l);
        g_w1TH[j * 64 + c] = h; g_w1TL[j * 64 + c] = l;
    }
}

// ---------------- DFT MMA core (8 warps) -------------------------------------
__device__ __forceinline__ void dft_core8(uint32_t sb, int VHo, int VLo, int BHo, int BLo,
                                          int wid, int lane, size_t pfbase) {
    int lr = lane & 7, li = lane >> 3;
    int drA = (li & 1) * 8, dcA = (li >> 1) * 16;
    int jt = (wid & 1) * 16;
    int cb2 = (wid >> 1) * 32;
    float f[2][4];
#pragma unroll
    for (int i = 0; i < 2; i++)
#pragma unroll
        for (int k = 0; k < 4; k++) f[i][k] = 0.0f;

#pragma unroll
    for (int s = 0; s < 8; s++) {
        int half = s >> 2, kb = (s & 3) * 32;
        uint32_t ah[4], al[4], bh[4], bl[4];
        ldsm4(sb + BHo + half * 4096 + SWZ((jt + drA + lr) * 128 + kb + dcA), ah);
        ldsm4(sb + BLo + half * 4096 + SWZ((jt + drA + lr) * 128 + kb + dcA), al);
        ldsm4t(sb + VHo + SWZ((16 * s + drA + lr) * 128 + cb2 + dcA), bh);
        ldsm4t(sb + VLo + SWZ((16 * s + drA + lr) * 128 + cb2 + dcA), bl);
        mma16816(f[0], ah, bh); mma16816(f[1], ah, bh + 2);
        mma16816(f[0], al, bh); mma16816(f[1], al, bh + 2);
        mma16816(f[0], ah, bl); mma16816(f[1], ah, bl + 2);
    }
    int q = lane & 3, g = lane >> 2;
    int cbase = (wid >> 1) * 16;
#pragma unroll
    for (int i = 0; i < 2; i++) {
        int c = cbase + i * 8 + 2 * q;
        int j = jt + g;
        *(float2*)&g_pF[(pfbase + j) * 64 + c]     = make_float2(f[i][0], f[i][1]);
        *(float2*)&g_pF[(pfbase + j + 8) * 64 + c] = make_float2(f[i][2], f[i][3]);
    }
}

// ---------------- fused fc0 + DFT --------------------------------------------
#define F0_VH 0
#define F0_VL 16384
#define F0_BH 32768
#define F0_BL 40960
#define F0_W0 49152
#define F0_SZ 50176

__global__ __launch_bounds__(256, 3)
void fc0dft_kernel(const float* __restrict__ xg, const float* __restrict__ tg,
                   const float* __restrict__ w0, const float* __restrict__ b0) {
    extern __shared__ char smc[];
    uint32_t sb = smem_u32(smc);
    float* w0s = (float*)(smc + F0_W0);
    float* b0s = w0s + 128;
    int tid = threadIdx.x, wid = tid >> 5, lane = tid & 31;
    int b = blockIdx.y, n0 = blockIdx.x * NT;

    for (int i = tid; i < 512; i += 256) {
        int half = i >> 8, rest = i & 255, j = rest >> 3, q = rest & 7;
        uint32_t so = half * 4096 + SWZ(j * 128 + q * 16);
        cpa16(sb + F0_BH + so, (const uint4*)(g_basDH + (size_t)j * NN + n0 + half * 64) + q);
        cpa16(sb + F0_BL + so, (const uint4*)(g_basDL + (size_t)j * NN + n0 + half * 64) + q);
    }
    CPA_COMMIT();
    if (tid < 128) w0s[tid] = w0[tid];
    if (tid < 64)  b0s[tid] = b0[tid];
    __syncthreads();

    int n = tid >> 1, c0 = (tid & 1) * 32;
    float xv = xg[(size_t)b * NN + n0 + n], tv = tg[(size_t)b * NN + n0 + n];
    uint32_t hw[16], lw[16];
#pragma unroll
    for (int k = 0; k < 16; k++) {
        int c = c0 + 2 * k;
        float v0 = fmaf(w0s[c],     xv, fmaf(w0s[64 + c],     tv, b0s[c]));
        float v1 = fmaf(w0s[c + 1], xv, fmaf(w0s[64 + c + 1], tv, b0s[c + 1]));
        bf16 h0, l0, h1, l1;
        split_bf(v0, h0, l0);
        split_bf(v1, h1, l1);
        hw[k] = pack_bf(h0, h1);
        lw[k] = pack_bf(l0, l1);
    }
    size_t ro = ((size_t)b * NN + n0 + n) * 64 + c0;
#pragma unroll
    for (int g4 = 0; g4 < 4; g4++) {
        uint4 hv = make_uint4(hw[4 * g4], hw[4 * g4 + 1], hw[4 * g4 + 2], hw[4 * g4 + 3]);
        uint4 lv = make_uint4(lw[4 * g4], lw[4 * g4 + 1], lw[4 * g4 + 2], lw[4 * g4 + 3]);
        *(uint4*)(g_hH0 + ro + 8 * g4) = hv;
        *(uint4*)(g_hL0 + ro + 8 * g4) = lv;
        uint32_t so = SWZ(n * 128 + c0 * 2 + g4 * 16);
        *(uint4*)(smc + F0_VH + so) = hv;
        *(uint4*)(smc + F0_VL + so) = lv;
    }
    CPA_WAIT(0);
    __syncthreads();
    dft_core8(sb, F0_VH, F0_VL, F0_BH, F0_BL, wid, lane,
              ((size_t)b * TBC + blockIdx.x) * J2);
}

// ---------------- reduce (R11 config) + modemix ------------------------------
__global__ __launch_bounds__(256)
void reduce_kernel() {
    int b = blockIdx.x;
    int idx = blockIdx.y * 256 + threadIdx.x;
    const float* p = &g_pF[(size_t)b * TBC * 2048 + idx];
    float s = 0.0f;
#pragma unroll 8
    for (int ch = 0; ch < TBC; ch++) s += p[(size_t)ch * 2048];
    g_F[(size_t)b * 2048 + idx] = s;
}

__global__ __launch_bounds__(1024)
void modemix_kernel(const float* __restrict__ swr,
                    const float* __restrict__ swi) {
    __shared__ float fs[64 * 33];   // [c][j]
    int b = blockIdx.x, tid = threadIdx.x;
    for (int idx = tid; idx < 2048; idx += 1024) {
        int j = idx >> 6, c = idx & 63;
        fs[c * 33 + j] = g_F[(size_t)b * 2048 + idx];
    }
    __syncthreads();
    int m = tid & 15, o = tid >> 4;
    float re = 0.0f, im = 0.0f;
    for (int i = 0; i < 64; i++) {
        float fr = fs[i * 33 + 2 * m];
        float fn = fs[i * 33 + 2 * m + 1];
        float wr = swr[(i * 64 + o) * 16 + m];
        float wi = swi[(i * 64 + o) * 16 + m];
        re = fmaf(fr, wr, fmaf(fn, wi, re));
        im = fmaf(fr, wi, fmaf(-fn, wr, im));
    }
    float cm = (m == 0 ? 1.0f : 2.0f) / (float)NN;
    float g0 = cm * re;
    float g1 = -cm * im;
    size_t r = ((size_t)b * 64 + o) * 64;
    bf16 h, l;
    split_bf(g0, h, l);
    g_GpP[r + 2 * m] = h;      g_GpP[r + 32 + 2 * m] = l;
    split_bf(g1, h, l);
    g_GpP[r + 2 * m + 1] = h;  g_GpP[r + 32 + 2 * m + 1] = l;
}

// ---------------- shared smem layout for layer kernels -----------------------
#define MM_HH  0
#define MM_HL  16384
#define MM_WH  32768
#define MM_WL  40960
#define MM_BDH 49152
#define MM_BDL 57344
#define MM_G   65536
#define MM_CB  73728
#define MM_SZ  73984
// layer3fc extras (regions reused): W1H at 32768, W1L at 49152 (post-GEMM)
#define M3_B1  73728    // 128 f
#define M3_W2  74240    // 128 f
#define M3_CB  74752    // 64 f
#define M3_SZ  75008

// common GEMM body: conv 3-term + synthesis 3-half-term into acc[8][4]
__device__ __forceinline__ void layer_gemm(uint32_t sb, int wid, int lane, float acc[8][4]) {
    int lr = lane & 7, li = lane >> 3;
    int drA = (li & 1) * 8, dcA = (li >> 1) * 16;
    int drB = (li >> 1) * 8, dcB = (li & 1) * 16;
    int rA0 = 16 * wid;

#pragma unroll
    for (int s = 0; s < 4; s++) {
        int kb = s * 32;
        uint32_t ah[4], al[4];
        ldsm4(sb + MM_HH + SWZ((rA0 + drA + lr) * 128 + kb + dcA), ah);
        ldsm4(sb + MM_HL + SWZ((rA0 + drA + lr) * 128 + kb + dcA), al);
#pragma unroll
        for (int np = 0; np < 4; np++) {
            uint32_t bb[4];
            ldsm4(sb + MM_WH + SWZ((np * 16 + drB + lr) * 128 + kb + dcB), bb);
            mma16816(acc[2 * np],     ah, bb);
            mma16816(acc[2 * np + 1], ah, bb + 2);
            mma16816(acc[2 * np],     al, bb);
            mma16816(acc[2 * np + 1], al, bb + 2);
            ldsm4(sb + MM_WL + SWZ((np * 16 + drB + lr) * 128 + kb + dcB), bb);
            mma16816(acc[2 * np],     ah, bb);
            mma16816(acc[2 * np + 1], ah, bb + 2);
        }
    }
    CPA_WAIT(0);
    __syncthreads();

    {
        int halfS = rA0 >> 6;
        int colA = (rA0 & 63) * 2 + (li & 1) * 16;
        int rowA = (li >> 1) * 8 + lr;
#pragma unroll
        for (int s = 0; s < 2; s++) {
            int kb = s * 32;
            uint32_t ah[4], al[4];
            ldsm4t(sb + MM_BDH + halfS * 4096 + SWZ((s * 16 + rowA) * 128 + colA), ah);
            ldsm4t(sb + MM_BDL + halfS * 4096 + SWZ((s * 16 + rowA) * 128 + colA), al);
#pragma unroll
            for (int np = 0; np < 4; np++) {
                uint32_t bb[4];
                ldsm4(sb + MM_G + SWZ((np * 16 + drB + lr) * 128 + kb + dcB), bb);
                mma16816(acc[2 * np],     ah, bb);
                mma16816(acc[2 * np + 1], ah, bb + 2);
                mma16816(acc[2 * np],     al, bb);
                mma16816(acc[2 * np + 1], al, bb + 2);
                ldsm4(sb + MM_G + SWZ((np * 16 + drB + lr) * 128 + 64 + kb + dcB), bb);
                mma16816(acc[2 * np],     ah, bb);
                mma16816(acc[2 * np + 1], ah, bb + 2);
            }
        }
    }
}

// common operand loads (groups A+B) for layer kernels
__device__ __forceinline__ void layer_loads(uint32_t sb, int tid, int layer, int b, int n0,
                                            const bf16* hHsrc, const bf16* hLsrc) {
    for (int i = tid; i < 1024; i += 256) {
        int r = i >> 3, q = i & 7;
        uint32_t so = SWZ(r * 128 + q * 16);
        cpa16(sb + MM_HH + so, (const uint4*)(hHsrc + (size_t)r * 64) + q);
        cpa16(sb + MM_HL + so, (const uint4*)(hLsrc + (size_t)r * 64) + q);
    }
    for (int i = tid; i < 512; i += 256) {
        int r = i >> 3, q = i & 7;
        uint32_t so = SWZ(r * 128 + q * 16);
        cpa16(sb + MM_WH + so, (const uint4*)(g_cwH + (size_t)(layer * 64 + r) * 64) + q);
        cpa16(sb + MM_WL + so, (const uint4*)(g_cwL + (size_t)(layer * 64 + r) * 64) + q);
    }
    CPA_COMMIT();
    for (int i = tid; i < 512; i += 256) {
        int r = i >> 3, q = i & 7;
        uint32_t so = SWZ(r * 128 + q * 16);
        cpa16(sb + MM_G + so, (const uint4*)(g_GpP + ((size_t)b * 64 + r) * 64) + q);
        int half = i >> 8, rest = i & 255, j = rest >> 3, qq = rest & 7;
        uint32_t so2 = half * 4096 + SWZ(j * 128 + qq * 16);
        cpa16(sb + MM_BDH + so2, (const uint4*)(g_basDH + (size_t)j * NN + n0 + half * 64) + qq);
        cpa16(sb + MM_BDL + so2, (const uint4*)(g_basDL + (size_t)j * NN + n0 + half * 64) + qq);
    }
    CPA_COMMIT();
}

// ---------------- fused layer 0-2: conv + synthesis + gelu + DFT --------------
__global__ __launch_bounds__(256, 3)
void mma_layer(int dir, int layer, int rev, const float* __restrict__ cb_all) {
    extern __shared__ char smc[];
    uint32_t sb = smem_u32(smc);
    int tid = threadIdx.x, wid = tid >> 5, lane = tid & 31;
    int b   = rev ? (BB - 1 - (int)blockIdx.y) : (int)blockIdx.y;
    int chk = rev ? (TBC - 1 - (int)blockIdx.x) : (int)blockIdx.x;
    int n0 = chk * NT;

    const bf16* hHsrc = (dir ? g_hH1 : g_hH0) + ((size_t)b * NN + n0) * 64;
    const bf16* hLsrc = (dir ? g_hL1 : g_hL0) + ((size_t)b * NN + n0) * 64;
    bf16* hHdst = (dir ? g_hH0 : g_hH1) + ((size_t)b * NN + n0) * 64;
    bf16* hLdst = (dir ? g_hL0 : g_hL1) + ((size_t)b * NN + n0) * 64;

    layer_loads(sb, tid, layer, b, n0, hHsrc, hLsrc);
    if (tid < 64) ((float*)(smc + MM_CB))[tid] = cb_all[layer * 64 + tid];
    CPA_WAIT(1);
    __syncthreads();

    float acc[8][4];
#pragma unroll
    for (int nt = 0; nt < 8; nt++)
#pragma unroll
        for (int k = 0; k < 4; k++) acc[nt][k] = 0.0f;

    layer_gemm(sb, wid, lane, acc);
    __syncthreads();

    // epilogue: bias + gelu, write vH/vL into HH/HL
    int q = lane & 3, g = lane >> 2;
    const float* cbs = (const float*)(smc + MM_CB);
#pragma unroll
    for (int nt = 0; nt < 8; nt++) {
        int o0 = nt * 8 + 2 * q;
        int r0 = 16 * wid + g;
        float v0 = gelu_exact(acc[nt][0] + cbs[o0]);
        float v1 = gelu_exact(acc[nt][1] + cbs[o0 + 1]);
        float v2 = gelu_exact(acc[nt][2] + cbs[o0]);
        float v3 = gelu_exact(acc[nt][3] + cbs[o0 + 1]);
        bf16 h0, l0, h1, l1;
        split_bf(v0, h0, l0); split_bf(v1, h1, l1);
        *(uint32_t*)(smc + MM_HH + SWZ(r0 * 128 + o0 * 2)) = pack_bf(h0, h1);
        *(uint32_t*)(smc + MM_HL + SWZ(r0 * 128 + o0 * 2)) = pack_bf(l0, l1);
        split_bf(v2, h0, l0); split_bf(v3, h1, l1);
        *(uint32_t*)(smc + MM_HH + SWZ((r0 + 8) * 128 + o0 * 2)) = pack_bf(h0, h1);
        *(uint32_t*)(smc + MM_HL + SWZ((r0 + 8) * 128 + o0 * 2)) = pack_bf(l0, l1);
    }
    __syncthreads();

    for (int i = tid; i < 1024; i += 256) {
        int r = i >> 3, qq = i & 7;
        uint32_t so = SWZ(r * 128 + qq * 16);
        ((uint4*)(hHdst + (size_t)r * 64))[qq] = *(uint4*)(smc + MM_HH + so);
        ((uint4*)(hLdst + (size_t)r * 64))[qq] = *(uint4*)(smc + MM_HL + so);
    }
    dft_core8(sb, MM_HH, MM_HL, MM_BDH, MM_BDL, wid, lane,
              ((size_t)b * TBC + chk) * J2);
}

// ---------------- fused layer 3 + fc1 + gelu + fc2 ---------------------------
__global__ __launch_bounds__(256, 2)
void mma_layer3fc(const float* __restrict__ cb_all,
                  const float* __restrict__ b1, const float* __restrict__ w2,
                  const float* __restrict__ b2, float* __restrict__ out) {
    extern __shared__ char smc[];
    uint32_t sb = smem_u32(smc);
    int tid = threadIdx.x, wid = tid >> 5, lane = tid & 31;
    int b = blockIdx.y, n0 = blockIdx.x * NT;   // forward (layer 2 ran reversed)

    const bf16* hHsrc = g_hH1 + ((size_t)b * NN + n0) * 64;
    const bf16* hLsrc = g_hL1 + ((size_t)b * NN + n0) * 64;

    layer_loads(sb, tid, 3, b, n0, hHsrc, hLsrc);
    if (tid < 64)  ((float*)(smc + M3_CB))[tid] = cb_all[3 * 64 + tid];
    if (tid < 128) {
        ((float*)(smc + M3_B1))[tid] = b1[tid];
        ((float*)(smc + M3_W2))[tid] = w2[tid];
    }
    CPA_WAIT(1);
    __syncthreads();

    float acc[8][4];
#pragma unroll
    for (int nt = 0; nt < 8; nt++)
#pragma unroll
        for (int k = 0; k < 4; k++) acc[nt][k] = 0.0f;

    layer_gemm(sb, wid, lane, acc);
    __syncthreads();   // weight/basis regions now dead

    // prefetch w1 into dead regions [32768, 65536)
    for (int i = tid; i < 2048; i += 256) {
        int buf = i >> 10, rest = i & 1023, r = rest >> 3, q = rest & 7;
        uint32_t so = SWZ(r * 128 + q * 16);
        const bf16* src = buf ? g_w1TL : g_w1TH;
        cpa16(sb + 32768 + buf * 16384 + so, (const uint4*)(src + (size_t)r * 64) + q);
    }
    CPA_COMMIT();

    // epilogue: v = acc + cb (no gelu), write split into HH/HL
    int q = lane & 3, g = lane >> 2;
    const float* cbs = (const float*)(smc + M3_CB);
#pragma unroll
    for (int nt = 0; nt < 8; nt++) {
        int o0 = nt * 8 + 2 * q;
        int r0 = 16 * wid + g;
        float v0 = acc[nt][0] + cbs[o0];
        float v1 = acc[nt][1] + cbs[o0 + 1];
        float v2 = acc[nt][2] + cbs[o0];
        float v3 = acc[nt][3] + cbs[o0 + 1];
        bf16 h0, l0, h1, l1;
        split_bf(v0, h0, l0); split_bf(v1, h1, l1);
        *(uint32_t*)(smc + MM_HH + SWZ(r0 * 128 + o0 * 2)) = pack_bf(h0, h1);
        *(uint32_t*)(smc + MM_HL + SWZ(r0 * 128 + o0 * 2)) = pack_bf(l0, l1);
        split_bf(v2, h0, l0); split_bf(v3, h1, l1);
        *(uint32_t*)(smc + MM_HH + SWZ((r0 + 8) * 128 + o0 * 2)) = pack_bf(h0, h1);
        *(uint32_t*)(smc + MM_HL + SWZ((r0 + 8) * 128 + o0 * 2)) = pack_bf(l0, l1);
    }
    CPA_WAIT(0);
    __syncthreads();

    // fc1: (vH+vL)·(w1H+w1L) 3-term, M=16 rows/warp, N=128, K=64
    int lr = lane & 7, li = lane >> 3;
    int drA = (li & 1) * 8, dcA = (li >> 1) * 16;
    int drB = (li >> 1) * 8, dcB = (li & 1) * 16;
    int rA0 = 16 * wid;
    const uint32_t W1H = sb + 32768, W1L = sb + 49152;

    float fac[16][4];
#pragma unroll
    for (int nt = 0; nt < 16; nt++)
#pragma unroll
        for (int k = 0; k < 4; k++) fac[nt][k] = 0.0f;

#pragma unroll
    for (int s = 0; s < 4; s++) {
        int kb = s * 32;
        uint32_t ah[4], al[4];
        ldsm4(sb + MM_HH + SWZ((rA0 + drA + lr) * 128 + kb + dcA), ah);
        ldsm4(sb + MM_HL + SWZ((rA0 + drA + lr) * 128 + kb + dcA), al);
#pragma unroll
        for (int np = 0; np < 8; np++) {
            uint32_t bb[4];
            ldsm4(W1H + SWZ((np * 16 + drB + lr) * 128 + kb + dcB), bb);
            mma16816(fac[2 * np],     ah, bb);
            mma16816(fac[2 * np + 1], ah, bb + 2);
            mma16816(fac[2 * np],     al, bb);
            mma16816(fac[2 * np + 1], al, bb + 2);
            ldsm4(W1L + SWZ((np * 16 + drB + lr) * 128 + kb + dcB), bb);
            mma16816(fac[2 * np],     ah, bb);
            mma16816(fac[2 * np + 1], ah, bb + 2);
        }
    }

    const float* b1s = (const float*)(smc + M3_B1);
    const float* w2s = (const float*)(smc + M3_W2);
    float s0 = 0.0f, s1 = 0.0f;
#pragma unroll
    for (int nt = 0; nt < 16; nt++) {
        int j0 = nt * 8 + 2 * q;
        s0 = fmaf(w2s[j0],     gelu_exact(fac[nt][0] + b1s[j0]),     s0);
        s0 = fmaf(w2s[j0 + 1], gelu_exact(fac[nt][1] + b1s[j0 + 1]), s0);
        s1 = fmaf(w2s[j0],     gelu_exact(fac[nt][2] + b1s[j0]),     s1);
        s1 = fmaf(w2s[j0 + 1], gelu_exact(fac[nt][3] + b1s[j0 + 1]), s1);
    }
    s0 += __shfl_xor_sync(0xffffffffu, s0, 1);
    s0 += __shfl_xor_sync(0xffffffffu, s0, 2);
    s1 += __shfl_xor_sync(0xffffffffu, s1, 1);
    s1 += __shfl_xor_sync(0xffffffffu, s1, 2);
    if (q == 0) {
        float bv = b2[0];
        out[(size_t)b * NN + n0 + 16 * wid + g]     = s0 + bv;
        out[(size_t)b * NN + n0 + 16 * wid + g + 8] = s1 + bv;
    }
}

// ---------------- host launcher ----------------------------------------------
extern "C" void kernel_launch(void* const* d_in, const int* in_sizes, int n_in,
                              void* d_out, int out_size) {
    const float* x    = (const float*)d_in[0];
    const float* t    = (const float*)d_in[1];
    const float* fc0w = (const float*)d_in[2];
    const float* fc0b = (const float*)d_in[3];
    const float* swr  = (const float*)d_in[4];
    const float* swi  = (const float*)d_in[5];
    const float* cw   = (const float*)d_in[6];
    const float* cb   = (const float*)d_in[7];
    const float* w1   = (const float*)d_in[8];
    const float* b1   = (const float*)d_in[9];
    const float* w2   = (const float*)d_in[10];
    const float* b2   = (const float*)d_in[11];
    float* out = (float*)d_out;

    cudaFuncSetAttribute(mma_layer,    cudaFuncAttributeMaxDynamicSharedMemorySize, MM_SZ);
    cudaFuncSetAttribute(mma_layer3fc, cudaFuncAttributeMaxDynamicSharedMemorySize, M3_SZ);
    cudaFuncSetAttribute(fc0dft_kernel, cudaFuncAttributeMaxDynamicSharedMemorySize, F0_SZ);

    dim3 g(TBC, BB);
    dim3 gr(BB, 8);
    prep_all<<<(NN + 4 * 4096 + 128 * 64 + 255) / 256, 256>>>(cw, w1);

    fc0dft_kernel<<<g, 256, F0_SZ>>>(x, t, fc0w, fc0b);      // forward

    const size_t SWL = (size_t)64 * 64 * 16;
    reduce_kernel<<<gr, 256>>>();
    modemix_kernel<<<BB, 1024>>>(swr + 0 * SWL, swi + 0 * SWL);
    mma_layer<<<g, 256, MM_SZ>>>(0, 0, 1, cb);               // reversed

    reduce_kernel<<<gr, 256>>>();
    modemix_kernel<<<BB, 1024>>>(swr + 1 * SWL, swi + 1 * SWL);
    mma_layer<<<g, 256, MM_SZ>>>(1, 1, 0, cb);               // forward

    reduce_kernel<<<gr, 256>>>();
    modemix_kernel<<<BB, 1024>>>(swr + 2 * SWL, swi + 2 * SWL);
    mma_layer<<<g, 256, MM_SZ>>>(0, 2, 1, cb);               // reversed

    reduce_kernel<<<gr, 256>>>();
    modemix_kernel<<<BB, 1024>>>(swr + 3 * SWL, swi + 3 * SWL);
    mma_layer3fc<<<g, 256, M3_SZ>>>(cb, b1, w2, b2, out);    // forward, fused
}

// round 14
// speedup vs baseline: 1.0895x; 1.0096x over previous
#include <cuda_runtime.h>
#include <cuda_bf16.h>
#include <math.h>
#include <stdint.h>
#include <stddef.h>

#define BB 64
#define NN 8192
#define MODES 16
#define J2 32
#define NT 128
#define TBC (NN / NT)

typedef __nv_bfloat16 bf16;

// ---------------- device scratch --------------------------------------------
__device__ bf16  g_hH0[(size_t)BB * NN * 64];
__device__ bf16  g_hL0[(size_t)BB * NN * 64];
__device__ bf16  g_hH1[(size_t)BB * NN * 64];
__device__ bf16  g_hL1[(size_t)BB * NN * 64];
__device__ float g_pF[(size_t)BB * TBC * J2 * 64];    // [b][chunk][j][c]
__device__ float g_F[(size_t)BB * J2 * 64];           // [b][j][c]
__device__ bf16  g_basDH[(size_t)J2 * NN];            // [j][n] hi
__device__ bf16  g_basDL[(size_t)J2 * NN];            // [j][n] lo
__device__ bf16  g_cwH[4 * 64 * 64];                  // [l][o][c]
__device__ bf16  g_cwL[4 * 64 * 64];
__device__ bf16  g_GpP[(size_t)BB * 64 * 64];         // [b][o][ gh(32) | gl(32) ]
__device__ bf16  g_w1TH[128 * 64];                    // [j][c]
__device__ bf16  g_w1TL[128 * 64];

// ---------------- helpers ----------------------------------------------------
#define SWZ(x) ((x) ^ (((x) >> 3) & 0x70))

__device__ __forceinline__ uint32_t smem_u32(const void* p) {
    uint32_t a;
    asm("{ .reg .u64 t; cvta.to.shared.u64 t, %1; cvt.u32.u64 %0, t; }" : "=r"(a) : "l"(p));
    return a;
}
__device__ __forceinline__ void cpa16(uint32_t dst, const void* src) {
    asm volatile("cp.async.cg.shared.global [%0], [%1], 16;" :: "r"(dst), "l"(src));
}
#define CPA_COMMIT() asm volatile("cp.async.commit_group;" ::: "memory")
#define CPA_WAIT(n)  asm volatile("cp.async.wait_group %0;" :: "n"(n) : "memory")

__device__ __forceinline__ void ldsm4(uint32_t a, uint32_t* r) {
    asm volatile("ldmatrix.sync.aligned.m8n8.x4.shared.b16 {%0,%1,%2,%3}, [%4];"
                 : "=r"(r[0]), "=r"(r[1]), "=r"(r[2]), "=r"(r[3]) : "r"(a));
}
__device__ __forceinline__ void ldsm4t(uint32_t a, uint32_t* r) {
    asm volatile("ldmatrix.sync.aligned.m8n8.x4.trans.shared.b16 {%0,%1,%2,%3}, [%4];"
                 : "=r"(r[0]), "=r"(r[1]), "=r"(r[2]), "=r"(r[3]) : "r"(a));
}
__device__ __forceinline__ void mma16816(float* d, const uint32_t* a, const uint32_t* b) {
    asm volatile(
        "mma.sync.aligned.m16n8k16.row.col.f32.bf16.bf16.f32 "
        "{%0,%1,%2,%3},{%4,%5,%6,%7},{%8,%9},{%0,%1,%2,%3};"
        : "+f"(d[0]), "+f"(d[1]), "+f"(d[2]), "+f"(d[3])
        : "r"(a[0]), "r"(a[1]), "r"(a[2]), "r"(a[3]), "r"(b[0]), "r"(b[1]));
}
__device__ __forceinline__ float gelu_exact(float v) {
    return 0.5f * v * (1.0f + erff(v * 0.70710678118654752f));
}
__device__ __forceinline__ void split_bf(float v, bf16& h, bf16& l) {
    h = __float2bfloat16(v);
    l = __float2bfloat16(v - __bfloat162float(h));
}
__device__ __forceinline__ uint32_t pack_bf(bf16 a, bf16 b) {
    return (uint32_t)__bfloat16_as_ushort(a) | ((uint32_t)__bfloat16_as_ushort(b) << 16);
}

// ---------------- merged prep (one launch) -----------------------------------
__global__ void prep_all(const float* __restrict__ cw, const float* __restrict__ w1) {
    int gidx = blockIdx.x * 256 + threadIdx.x;
    if (gidx < NN) {
        int n = gidx;
#pragma unroll
        for (int m = 0; m < MODES; m++) {
            int r = (m * n) & (NN - 1);
            float tf = 2.0f * (float)r / (float)NN;
            float s, c;
            sincospif(tf, &s, &c);
            bf16 h, l;
            split_bf(c, h, l);
            g_basDH[(size_t)(2 * m) * NN + n] = h;
            g_basDL[(size_t)(2 * m) * NN + n] = l;
            split_bf(s, h, l);
            g_basDH[(size_t)(2 * m + 1) * NN + n] = h;
            g_basDL[(size_t)(2 * m + 1) * NN + n] = l;
        }
    } else if (gidx < NN + 4 * 64 * 64) {
        int idx = gidx - NN;
        bf16 h, l;
        split_bf(cw[idx], h, l);
        g_cwH[idx] = h; g_cwL[idx] = l;
    } else if (gidx < NN + 4 * 64 * 64 + 128 * 64) {
        int i2 = gidx - NN - 4 * 64 * 64;
        int c = i2 >> 7, j = i2 & 127;
        bf16 h, l;
        split_bf(w1[c * 128 + j], h, l);
        g_w1TH[j * 64 + c] = h; g_w1TL[j * 64 + c] = l;
    }
}

// ---------------- DFT MMA core (8 warps) -------------------------------------
__device__ __forceinline__ void dft_core8(uint32_t sb, int VHo, int VLo, int BHo, int BLo,
                                          int wid, int lane, size_t pfbase) {
    int lr = lane & 7, li = lane >> 3;
    int drA = (li & 1) * 8, dcA = (li >> 1) * 16;
    int jt = (wid & 1) * 16;
    int cb2 = (wid >> 1) * 32;
    float f[2][4];
#pragma unroll
    for (int i = 0; i < 2; i++)
#pragma unroll
        for (int k = 0; k < 4; k++) f[i][k] = 0.0f;

#pragma unroll
    for (int s = 0; s < 8; s++) {
        int half = s >> 2, kb = (s & 3) * 32;
        uint32_t ah[4], al[4], bh[4], bl[4];
        ldsm4(sb + BHo + half * 4096 + SWZ((jt + drA + lr) * 128 + kb + dcA), ah);
        ldsm4(sb + BLo + half * 4096 + SWZ((jt + drA + lr) * 128 + kb + dcA), al);
        ldsm4t(sb + VHo + SWZ((16 * s + drA + lr) * 128 + cb2 + dcA), bh);
        ldsm4t(sb + VLo + SWZ((16 * s + drA + lr) * 128 + cb2 + dcA), bl);
        mma16816(f[0], ah, bh); mma16816(f[1], ah, bh + 2);
        mma16816(f[0], al, bh); mma16816(f[1], al, bh + 2);
        mma16816(f[0], ah, bl); mma16816(f[1], ah, bl + 2);
    }
    int q = lane & 3, g = lane >> 2;
    int cbase = (wid >> 1) * 16;
#pragma unroll
    for (int i = 0; i < 2; i++) {
        int c = cbase + i * 8 + 2 * q;
        int j = jt + g;
        *(float2*)&g_pF[(pfbase + j) * 64 + c]     = make_float2(f[i][0], f[i][1]);
        *(float2*)&g_pF[(pfbase + j + 8) * 64 + c] = make_float2(f[i][2], f[i][3]);
    }
}

// ---------------- fused fc0 + DFT --------------------------------------------
#define F0_VH 0
#define F0_VL 16384
#define F0_BH 32768
#define F0_BL 40960
#define F0_W0 49152
#define F0_SZ 50176

__global__ __launch_bounds__(256, 3)
void fc0dft_kernel(const float* __restrict__ xg, const float* __restrict__ tg,
                   const float* __restrict__ w0, const float* __restrict__ b0) {
    extern __shared__ char smc[];
    uint32_t sb = smem_u32(smc);
    float* w0s = (float*)(smc + F0_W0);
    float* b0s = w0s + 128;
    int tid = threadIdx.x, wid = tid >> 5, lane = tid & 31;
    int b = blockIdx.y, n0 = blockIdx.x * NT;

    for (int i = tid; i < 512; i += 256) {
        int half = i >> 8, rest = i & 255, j = rest >> 3, q = rest & 7;
        uint32_t so = half * 4096 + SWZ(j * 128 + q * 16);
        cpa16(sb + F0_BH + so, (const uint4*)(g_basDH + (size_t)j * NN + n0 + half * 64) + q);
        cpa16(sb + F0_BL + so, (const uint4*)(g_basDL + (size_t)j * NN + n0 + half * 64) + q);
    }
    CPA_COMMIT();
    if (tid < 128) w0s[tid] = w0[tid];
    if (tid < 64)  b0s[tid] = b0[tid];
    __syncthreads();

    int n = tid >> 1, c0 = (tid & 1) * 32;
    float xv = xg[(size_t)b * NN + n0 + n], tv = tg[(size_t)b * NN + n0 + n];
    uint32_t hw[16], lw[16];
#pragma unroll
    for (int k = 0; k < 16; k++) {
        int c = c0 + 2 * k;
        float v0 = fmaf(w0s[c],     xv, fmaf(w0s[64 + c],     tv, b0s[c]));
        float v1 = fmaf(w0s[c + 1], xv, fmaf(w0s[64 + c + 1], tv, b0s[c + 1]));
        bf16 h0, l0, h1, l1;
        split_bf(v0, h0, l0);
        split_bf(v1, h1, l1);
        hw[k] = pack_bf(h0, h1);
        lw[k] = pack_bf(l0, l1);
    }
    size_t ro = ((size_t)b * NN + n0 + n) * 64 + c0;
#pragma unroll
    for (int g4 = 0; g4 < 4; g4++) {
        uint4 hv = make_uint4(hw[4 * g4], hw[4 * g4 + 1], hw[4 * g4 + 2], hw[4 * g4 + 3]);
        uint4 lv = make_uint4(lw[4 * g4], lw[4 * g4 + 1], lw[4 * g4 + 2], lw[4 * g4 + 3]);
        *(uint4*)(g_hH0 + ro + 8 * g4) = hv;
        *(uint4*)(g_hL0 + ro + 8 * g4) = lv;
        uint32_t so = SWZ(n * 128 + c0 * 2 + g4 * 16);
        *(uint4*)(smc + F0_VH + so) = hv;
        *(uint4*)(smc + F0_VL + so) = lv;
    }
    CPA_WAIT(0);
    __syncthreads();
    dft_core8(sb, F0_VH, F0_VL, F0_BH, F0_BL, wid, lane,
              ((size_t)b * TBC + blockIdx.x) * J2);
}

// ---------------- reduce + modemix -------------------------------------------
__global__ __launch_bounds__(256)
void reduce_kernel() {
    int b = blockIdx.x;
    int idx = blockIdx.y * 256 + threadIdx.x;
    const float* p = &g_pF[(size_t)b * TBC * 2048 + idx];
    float s = 0.0f;
#pragma unroll 8
    for (int ch = 0; ch < TBC; ch++) s += p[(size_t)ch * 2048];
    g_F[(size_t)b * 2048 + idx] = s;
}

__global__ __launch_bounds__(1024)
void modemix_kernel(const float* __restrict__ swr,
                    const float* __restrict__ swi) {
    __shared__ float fs[64 * 33];   // [c][j]
    int b = blockIdx.x, tid = threadIdx.x;
    for (int idx = tid; idx < 2048; idx += 1024) {
        int j = idx >> 6, c = idx & 63;
        fs[c * 33 + j] = g_F[(size_t)b * 2048 + idx];
    }
    __syncthreads();
    int m = tid & 15, o = tid >> 4;
    float re = 0.0f, im = 0.0f;
#pragma unroll 4
    for (int i = 0; i < 64; i++) {
        float fr = fs[i * 33 + 2 * m];
        float fn = fs[i * 33 + 2 * m + 1];
        float wr = __ldg(&swr[(i * 64 + o) * 16 + m]);
        float wi = __ldg(&swi[(i * 64 + o) * 16 + m]);
        re = fmaf(fr, wr, fmaf(fn, wi, re));
        im = fmaf(fr, wi, fmaf(-fn, wr, im));
    }
    float cm = (m == 0 ? 1.0f : 2.0f) / (float)NN;
    float g0 = cm * re;
    float g1 = -cm * im;
    size_t r = ((size_t)b * 64 + o) * 64;
    bf16 h, l;
    split_bf(g0, h, l);
    g_GpP[r + 2 * m] = h;      g_GpP[r + 32 + 2 * m] = l;
    split_bf(g1, h, l);
    g_GpP[r + 2 * m + 1] = h;  g_GpP[r + 32 + 2 * m + 1] = l;
}

// ---------------- shared smem layout for layer kernels -----------------------
#define MM_HH  0
#define MM_HL  16384
#define MM_WH  32768
#define MM_WL  40960
#define MM_BDH 49152
#define MM_BDL 57344
#define MM_G   65536
#define MM_CB  73728
#define MM_SZ  73984
#define M3_B1  73728
#define M3_W2  74240
#define M3_CB  74752
#define M3_SZ  75008

__device__ __forceinline__ void layer_gemm(uint32_t sb, int wid, int lane, float acc[8][4]) {
    int lr = lane & 7, li = lane >> 3;
    int drA = (li & 1) * 8, dcA = (li >> 1) * 16;
    int drB = (li >> 1) * 8, dcB = (li & 1) * 16;
    int rA0 = 16 * wid;

#pragma unroll
    for (int s = 0; s < 4; s++) {
        int kb = s * 32;
        uint32_t ah[4], al[4];
        ldsm4(sb + MM_HH + SWZ((rA0 + drA + lr) * 128 + kb + dcA), ah);
        ldsm4(sb + MM_HL + SWZ((rA0 + drA + lr) * 128 + kb + dcA), al);
#pragma unroll
        for (int np = 0; np < 4; np++) {
            uint32_t bb[4];
            ldsm4(sb + MM_WH + SWZ((np * 16 + drB + lr) * 128 + kb + dcB), bb);
            mma16816(acc[2 * np],     ah, bb);
            mma16816(acc[2 * np + 1], ah, bb + 2);
            mma16816(acc[2 * np],     al, bb);
            mma16816(acc[2 * np + 1], al, bb + 2);
            ldsm4(sb + MM_WL + SWZ((np * 16 + drB + lr) * 128 + kb + dcB), bb);
            mma16816(acc[2 * np],     ah, bb);
            mma16816(acc[2 * np + 1], ah, bb + 2);
        }
    }
    CPA_WAIT(0);
    __syncthreads();

    {
        int halfS = rA0 >> 6;
        int colA = (rA0 & 63) * 2 + (li & 1) * 16;
        int rowA = (li >> 1) * 8 + lr;
#pragma unroll
        for (int s = 0; s < 2; s++) {
            int kb = s * 32;
            uint32_t ah[4], al[4];
            ldsm4t(sb + MM_BDH + halfS * 4096 + SWZ((s * 16 + rowA) * 128 + colA), ah);
            ldsm4t(sb + MM_BDL + halfS * 4096 + SWZ((s * 16 + rowA) * 128 + colA), al);
#pragma unroll
            for (int np = 0; np < 4; np++) {
                uint32_t bb[4];
                ldsm4(sb + MM_G + SWZ((np * 16 + drB + lr) * 128 + kb + dcB), bb);
                mma16816(acc[2 * np],     ah, bb);
                mma16816(acc[2 * np + 1], ah, bb + 2);
                mma16816(acc[2 * np],     al, bb);
                mma16816(acc[2 * np + 1], al, bb + 2);
                ldsm4(sb + MM_G + SWZ((np * 16 + drB + lr) * 128 + 64 + kb + dcB), bb);
                mma16816(acc[2 * np],     ah, bb);
                mma16816(acc[2 * np + 1], ah, bb + 2);
            }
        }
    }
}

__device__ __forceinline__ void layer_loads(uint32_t sb, int tid, int layer, int b, int n0,
                                            const bf16* hHsrc, const bf16* hLsrc) {
    for (int i = tid; i < 1024; i += 256) {
        int r = i >> 3, q = i & 7;
        uint32_t so = SWZ(r * 128 + q * 16);
        cpa16(sb + MM_HH + so, (const uint4*)(hHsrc + (size_t)r * 64) + q);
        cpa16(sb + MM_HL + so, (const uint4*)(hLsrc + (size_t)r * 64) + q);
    }
    for (int i = tid; i < 512; i += 256) {
        int r = i >> 3, q = i & 7;
        uint32_t so = SWZ(r * 128 + q * 16);
        cpa16(sb + MM_WH + so, (const uint4*)(g_cwH + (size_t)(layer * 64 + r) * 64) + q);
        cpa16(sb + MM_WL + so, (const uint4*)(g_cwL + (size_t)(layer * 64 + r) * 64) + q);
    }
    CPA_COMMIT();
    for (int i = tid; i < 512; i += 256) {
        int r = i >> 3, q = i & 7;
        uint32_t so = SWZ(r * 128 + q * 16);
        cpa16(sb + MM_G + so, (const uint4*)(g_GpP + ((size_t)b * 64 + r) * 64) + q);
        int half = i >> 8, rest = i & 255, j = rest >> 3, qq = rest & 7;
        uint32_t so2 = half * 4096 + SWZ(j * 128 + qq * 16);
        cpa16(sb + MM_BDH + so2, (const uint4*)(g_basDH + (size_t)j * NN + n0 + half * 64) + qq);
        cpa16(sb + MM_BDL + so2, (const uint4*)(g_basDL + (size_t)j * NN + n0 + half * 64) + qq);
    }
    CPA_COMMIT();
}

// ---------------- fused layer 0-2: conv + synthesis + gelu + DFT --------------
__global__ __launch_bounds__(256, 3)
void mma_layer(int dir, int layer, int rev, const float* __restrict__ cb_all) {
    extern __shared__ char smc[];
    uint32_t sb = smem_u32(smc);
    int tid = threadIdx.x, wid = tid >> 5, lane = tid & 31;
    int b   = rev ? (BB - 1 - (int)blockIdx.y) : (int)blockIdx.y;
    int chk = rev ? (TBC - 1 - (int)blockIdx.x) : (int)blockIdx.x;
    int n0 = chk * NT;

    const bf16* hHsrc = (dir ? g_hH1 : g_hH0) + ((size_t)b * NN + n0) * 64;
    const bf16* hLsrc = (dir ? g_hL1 : g_hL0) + ((size_t)b * NN + n0) * 64;
    bf16* hHdst = (dir ? g_hH0 : g_hH1) + ((size_t)b * NN + n0) * 64;
    bf16* hLdst = (dir ? g_hL0 : g_hL1) + ((size_t)b * NN + n0) * 64;

    layer_loads(sb, tid, layer, b, n0, hHsrc, hLsrc);
    if (tid < 64) ((float*)(smc + MM_CB))[tid] = cb_all[layer * 64 + tid];
    CPA_WAIT(1);
    __syncthreads();

    float acc[8][4];
#pragma unroll
    for (int nt = 0; nt < 8; nt++)
#pragma unroll
        for (int k = 0; k < 4; k++) acc[nt][k] = 0.0f;

    layer_gemm(sb, wid, lane, acc);
    __syncthreads();

    int q = lane & 3, g = lane >> 2;
    const float* cbs = (const float*)(smc + MM_CB);
#pragma unroll
    for (int nt = 0; nt < 8; nt++) {
        int o0 = nt * 8 + 2 * q;
        int r0 = 16 * wid + g;
        float v0 = gelu_exact(acc[nt][0] + cbs[o0]);
        float v1 = gelu_exact(acc[nt][1] + cbs[o0 + 1]);
        float v2 = gelu_exact(acc[nt][2] + cbs[o0]);
        float v3 = gelu_exact(acc[nt][3] + cbs[o0 + 1]);
        bf16 h0, l0, h1, l1;
        split_bf(v0, h0, l0); split_bf(v1, h1, l1);
        *(uint32_t*)(smc + MM_HH + SWZ(r0 * 128 + o0 * 2)) = pack_bf(h0, h1);
        *(uint32_t*)(smc + MM_HL + SWZ(r0 * 128 + o0 * 2)) = pack_bf(l0, l1);
        split_bf(v2, h0, l0); split_bf(v3, h1, l1);
        *(uint32_t*)(smc + MM_HH + SWZ((r0 + 8) * 128 + o0 * 2)) = pack_bf(h0, h1);
        *(uint32_t*)(smc + MM_HL + SWZ((r0 + 8) * 128 + o0 * 2)) = pack_bf(l0, l1);
    }
    __syncthreads();

    for (int i = tid; i < 1024; i += 256) {
        int r = i >> 3, qq = i & 7;
        uint32_t so = SWZ(r * 128 + qq * 16);
        ((uint4*)(hHdst + (size_t)r * 64))[qq] = *(uint4*)(smc + MM_HH + so);
        ((uint4*)(hLdst + (size_t)r * 64))[qq] = *(uint4*)(smc + MM_HL + so);
    }
    dft_core8(sb, MM_HH, MM_HL, MM_BDH, MM_BDL, wid, lane,
              ((size_t)b * TBC + chk) * J2);
}

// ---------------- fused layer 3 + fc1 + gelu + fc2 ---------------------------
__global__ __launch_bounds__(256, 3)
void mma_layer3fc(const float* __restrict__ cb_all,
                  const float* __restrict__ b1, const float* __restrict__ w2,
                  const float* __restrict__ b2, float* __restrict__ out) {
    extern __shared__ char smc[];
    uint32_t sb = smem_u32(smc);
    int tid = threadIdx.x, wid = tid >> 5, lane = tid & 31;
    int b = blockIdx.y, n0 = blockIdx.x * NT;   // forward (layer 2 ran reversed)

    const bf16* hHsrc = g_hH1 + ((size_t)b * NN + n0) * 64;
    const bf16* hLsrc = g_hL1 + ((size_t)b * NN + n0) * 64;

    layer_loads(sb, tid, 3, b, n0, hHsrc, hLsrc);
    if (tid < 64)  ((float*)(smc + M3_CB))[tid] = cb_all[3 * 64 + tid];
    if (tid < 128) {
        ((float*)(smc + M3_B1))[tid] = b1[tid];
        ((float*)(smc + M3_W2))[tid] = w2[tid];
    }
    CPA_WAIT(1);
    __syncthreads();

    float acc[8][4];
#pragma unroll
    for (int nt = 0; nt < 8; nt++)
#pragma unroll
        for (int k = 0; k < 4; k++) acc[nt][k] = 0.0f;

    layer_gemm(sb, wid, lane, acc);
    __syncthreads();   // weight/basis regions now dead

    // prefetch w1 into dead regions [32768, 65536)
    for (int i = tid; i < 2048; i += 256) {
        int buf = i >> 10, rest = i & 1023, r = rest >> 3, q = rest & 7;
        uint32_t so = SWZ(r * 128 + q * 16);
        const bf16* src = buf ? g_w1TL : g_w1TH;
        cpa16(sb + 32768 + buf * 16384 + so, (const uint4*)(src + (size_t)r * 64) + q);
    }
    CPA_COMMIT();

    // epilogue: v = acc + cb (no gelu), split into HH/HL
    int q = lane & 3, g = lane >> 2;
    const float* cbs = (const float*)(smc + M3_CB);
#pragma unroll
    for (int nt = 0; nt < 8; nt++) {
        int o0 = nt * 8 + 2 * q;
        int r0 = 16 * wid + g;
        float v0 = acc[nt][0] + cbs[o0];
        float v1 = acc[nt][1] + cbs[o0 + 1];
        float v2 = acc[nt][2] + cbs[o0];
        float v3 = acc[nt][3] + cbs[o0 + 1];
        bf16 h0, l0, h1, l1;
        split_bf(v0, h0, l0); split_bf(v1, h1, l1);
        *(uint32_t*)(smc + MM_HH + SWZ(r0 * 128 + o0 * 2)) = pack_bf(h0, h1);
        *(uint32_t*)(smc + MM_HL + SWZ(r0 * 128 + o0 * 2)) = pack_bf(l0, l1);
        split_bf(v2, h0, l0); split_bf(v3, h1, l1);
        *(uint32_t*)(smc + MM_HH + SWZ((r0 + 8) * 128 + o0 * 2)) = pack_bf(h0, h1);
        *(uint32_t*)(smc + MM_HL + SWZ((r0 + 8) * 128 + o0 * 2)) = pack_bf(l0, l1);
    }
    CPA_WAIT(0);
    __syncthreads();

    // fc1 in two j-halves (register-lean) + gelu·w2 fold
    int lr = lane & 7, li = lane >> 3;
    int drA = (li & 1) * 8, dcA = (li >> 1) * 16;
    int drB = (li >> 1) * 8, dcB = (li & 1) * 16;
    int rA0 = 16 * wid;
    const uint32_t W1H = sb + 32768, W1L = sb + 49152;
    const float* b1s = (const float*)(smc + M3_B1);
    const float* w2s = (const float*)(smc + M3_W2);

    float s0 = 0.0f, s1 = 0.0f;
#pragma unroll
    for (int half = 0; half < 2; half++) {
        float fac[8][4];
#pragma unroll
        for (int nt = 0; nt < 8; nt++)
#pragma unroll
            for (int k = 0; k < 4; k++) fac[nt][k] = 0.0f;

#pragma unroll
        for (int s = 0; s < 4; s++) {
            int kb = s * 32;
            uint32_t ah[4], al[4];
            ldsm4(sb + MM_HH + SWZ((rA0 + drA + lr) * 128 + kb + dcA), ah);
            ldsm4(sb + MM_HL + SWZ((rA0 + drA + lr) * 128 + kb + dcA), al);
#pragma unroll
            for (int np = 0; np < 4; np++) {
                int npp = half * 4 + np;
                uint32_t bb[4];
                ldsm4(W1H + SWZ((npp * 16 + drB + lr) * 128 + kb + dcB), bb);
                mma16816(fac[2 * np],     ah, bb);
                mma16816(fac[2 * np + 1], ah, bb + 2);
                mma16816(fac[2 * np],     al, bb);
                mma16816(fac[2 * np + 1], al, bb + 2);
                ldsm4(W1L + SWZ((npp * 16 + drB + lr) * 128 + kb + dcB), bb);
                mma16816(fac[2 * np],     ah, bb);
                mma16816(fac[2 * np + 1], ah, bb + 2);
            }
        }
#pragma unroll
        for (int nt = 0; nt < 8; nt++) {
            int j0 = half * 64 + nt * 8 + 2 * q;
            s0 = fmaf(w2s[j0],     gelu_exact(fac[nt][0] + b1s[j0]),     s0);
            s0 = fmaf(w2s[j0 + 1], gelu_exact(fac[nt][1] + b1s[j0 + 1]), s0);
            s1 = fmaf(w2s[j0],     gelu_exact(fac[nt][2] + b1s[j0]),     s1);
            s1 = fmaf(w2s[j0 + 1], gelu_exact(fac[nt][3] + b1s[j0 + 1]), s1);
        }
    }
    s0 += __shfl_xor_sync(0xffffffffu, s0, 1);
    s0 += __shfl_xor_sync(0xffffffffu, s0, 2);
    s1 += __shfl_xor_sync(0xffffffffu, s1, 1);
    s1 += __shfl_xor_sync(0xffffffffu, s1, 2);
    if (q == 0) {
        float bv = b2[0];
        out[(size_t)b * NN + n0 + 16 * wid + g]     = s0 + bv;
        out[(size_t)b * NN + n0 + 16 * wid + g + 8] = s1 + bv;
    }
}

// ---------------- host launcher ----------------------------------------------
extern "C" void kernel_launch(void* const* d_in, const int* in_sizes, int n_in,
                              void* d_out, int out_size) {
    const float* x    = (const float*)d_in[0];
    const float* t    = (const float*)d_in[1];
    const float* fc0w = (const float*)d_in[2];
    const float* fc0b = (const float*)d_in[3];
    const float* swr  = (const float*)d_in[4];
    const float* swi  = (const float*)d_in[5];
    const float* cw   = (const float*)d_in[6];
    const float* cb   = (const float*)d_in[7];
    const float* w1   = (const float*)d_in[8];
    const float* b1   = (const float*)d_in[9];
    const float* w2   = (const float*)d_in[10];
    const float* b2   = (const float*)d_in[11];
    float* out = (float*)d_out;

    cudaFuncSetAttribute(mma_layer,    cudaFuncAttributeMaxDynamicSharedMemorySize, MM_SZ);
    cudaFuncSetAttribute(mma_layer3fc, cudaFuncAttributeMaxDynamicSharedMemorySize, M3_SZ);
    cudaFuncSetAttribute(fc0dft_kernel, cudaFuncAttributeMaxDynamicSharedMemorySize, F0_SZ);

    dim3 g(TBC, BB);
    dim3 gr(BB, 8);
    prep_all<<<(NN + 4 * 4096 + 128 * 64 + 255) / 256, 256>>>(cw, w1);

    fc0dft_kernel<<<g, 256, F0_SZ>>>(x, t, fc0w, fc0b);      // forward

    const size_t SWL = (size_t)64 * 64 * 16;
    reduce_kernel<<<gr, 256>>>();
    modemix_kernel<<<BB, 1024>>>(swr + 0 * SWL, swi + 0 * SWL);
    mma_layer<<<g, 256, MM_SZ>>>(0, 0, 1, cb);               // reversed

    reduce_kernel<<<gr, 256>>>();
    modemix_kernel<<<BB, 1024>>>(swr + 1 * SWL, swi + 1 * SWL);
    mma_layer<<<g, 256, MM_SZ>>>(1, 1, 0, cb);               // forward

    reduce_kernel<<<gr, 256>>>();
    modemix_kernel<<<BB, 1024>>>(swr + 2 * SWL, swi + 2 * SWL);
    mma_layer<<<g, 256, MM_SZ>>>(0, 2, 1, cb);               // reversed

    reduce_kernel<<<gr, 256>>>();
    modemix_kernel<<<BB, 1024>>>(swr + 3 * SWL, swi + 3 * SWL);
    mma_layer3fc<<<g, 256, M3_SZ>>>(cb, b1, w2, b2, out);    // forward, fused
}

// round 16
// speedup vs baseline: 1.1110x; 1.0198x over previous
#include <cuda_runtime.h>
#include <cuda_bf16.h>
#include <math.h>
#include <stdint.h>
#include <stddef.h>

#define BB 64
#define NN 8192
#define MODES 16
#define J2 32
#define NT 128
#define TBC (NN / NT)

typedef __nv_bfloat16 bf16;

// ---------------- device scratch --------------------------------------------
__device__ bf16  g_hH0[(size_t)BB * NN * 64];
__device__ bf16  g_hL0[(size_t)BB * NN * 64];
__device__ bf16  g_hH1[(size_t)BB * NN * 64];
__device__ bf16  g_hL1[(size_t)BB * NN * 64];
__device__ float g_pF[(size_t)BB * TBC * J2 * 64];    // [b][chunk][j][c]
__device__ float g_F[(size_t)BB * J2 * 64];           // [b][j][c]
__device__ bf16  g_basDH[(size_t)J2 * NN];            // [j][n] hi
__device__ bf16  g_basDL[(size_t)J2 * NN];            // [j][n] lo
__device__ bf16  g_cwH[4 * 64 * 64];                  // [l][o][c]
__device__ bf16  g_cwL[4 * 64 * 64];
__device__ bf16  g_GpP[(size_t)BB * 64 * 64];         // [b][o][ gh(32) | gl(32) ]
__device__ bf16  g_w1TH[128 * 64];                    // [j][c]
__device__ bf16  g_w1TL[128 * 64];

// ---------------- helpers ----------------------------------------------------
#define SWZ(x) ((x) ^ (((x) >> 3) & 0x70))

__device__ __forceinline__ uint32_t smem_u32(const void* p) {
    uint32_t a;
    asm("{ .reg .u64 t; cvta.to.shared.u64 t, %1; cvt.u32.u64 %0, t; }" : "=r"(a) : "l"(p));
    return a;
}
__device__ __forceinline__ void cpa16(uint32_t dst, const void* src) {
    asm volatile("cp.async.cg.shared.global [%0], [%1], 16;" :: "r"(dst), "l"(src));
}
#define CPA_COMMIT() asm volatile("cp.async.commit_group;" ::: "memory")
#define CPA_WAIT(n)  asm volatile("cp.async.wait_group %0;" :: "n"(n) : "memory")

__device__ __forceinline__ void ldsm4(uint32_t a, uint32_t* r) {
    asm volatile("ldmatrix.sync.aligned.m8n8.x4.shared.b16 {%0,%1,%2,%3}, [%4];"
                 : "=r"(r[0]), "=r"(r[1]), "=r"(r[2]), "=r"(r[3]) : "r"(a));
}
__device__ __forceinline__ void ldsm4t(uint32_t a, uint32_t* r) {
    asm volatile("ldmatrix.sync.aligned.m8n8.x4.trans.shared.b16 {%0,%1,%2,%3}, [%4];"
                 : "=r"(r[0]), "=r"(r[1]), "=r"(r[2]), "=r"(r[3]) : "r"(a));
}
__device__ __forceinline__ void mma16816(float* d, const uint32_t* a, const uint32_t* b) {
    asm volatile(
        "mma.sync.aligned.m16n8k16.row.col.f32.bf16.bf16.f32 "
        "{%0,%1,%2,%3},{%4,%5,%6,%7},{%8,%9},{%0,%1,%2,%3};"
        : "+f"(d[0]), "+f"(d[1]), "+f"(d[2]), "+f"(d[3])
        : "r"(a[0]), "r"(a[1]), "r"(a[2]), "r"(a[3]), "r"(b[0]), "r"(b[1]));
}
__device__ __forceinline__ float gelu_exact(float v) {
    return 0.5f * v * (1.0f + erff(v * 0.70710678118654752f));
}
__device__ __forceinline__ void split_bf(float v, bf16& h, bf16& l) {
    h = __float2bfloat16(v);
    l = __float2bfloat16(v - __bfloat162float(h));
}
__device__ __forceinline__ uint32_t pack_bf(bf16 a, bf16 b) {
    return (uint32_t)__bfloat16_as_ushort(a) | ((uint32_t)__bfloat16_as_ushort(b) << 16);
}

// ---------------- merged prep (one launch) -----------------------------------
__global__ void prep_all(const float* __restrict__ cw, const float* __restrict__ w1) {
    int gidx = blockIdx.x * 256 + threadIdx.x;
    if (gidx < NN) {
        int n = gidx;
#pragma unroll
        for (int m = 0; m < MODES; m++) {
            int r = (m * n) & (NN - 1);
            float tf = 2.0f * (float)r / (float)NN;
            float s, c;
            sincospif(tf, &s, &c);
            bf16 h, l;
            split_bf(c, h, l);
            g_basDH[(size_t)(2 * m) * NN + n] = h;
            g_basDL[(size_t)(2 * m) * NN + n] = l;
            split_bf(s, h, l);
            g_basDH[(size_t)(2 * m + 1) * NN + n] = h;
            g_basDL[(size_t)(2 * m + 1) * NN + n] = l;
        }
    } else if (gidx < NN + 4 * 64 * 64) {
        int idx = gidx - NN;
        bf16 h, l;
        split_bf(cw[idx], h, l);
        g_cwH[idx] = h; g_cwL[idx] = l;
    } else if (gidx < NN + 4 * 64 * 64 + 128 * 64) {
        int i2 = gidx - NN - 4 * 64 * 64;
        int c = i2 >> 7, j = i2 & 127;
        bf16 h, l;
        split_bf(w1[c * 128 + j], h, l);
        g_w1TH[j * 64 + c] = h; g_w1TL[j * 64 + c] = l;
    }
}

// ---------------- DFT MMA core (8 warps) -------------------------------------
__device__ __forceinline__ void dft_core8(uint32_t sb, int VHo, int VLo, int BHo, int BLo,
                                          int wid, int lane, size_t pfbase) {
    int lr = lane & 7, li = lane >> 3;
    int drA = (li & 1) * 8, dcA = (li >> 1) * 16;
    int jt = (wid & 1) * 16;
    int cb2 = (wid >> 1) * 32;
    float f[2][4];
#pragma unroll
    for (int i = 0; i < 2; i++)
#pragma unroll
        for (int k = 0; k < 4; k++) f[i][k] = 0.0f;

#pragma unroll
    for (int s = 0; s < 8; s++) {
        int half = s >> 2, kb = (s & 3) * 32;
        uint32_t ah[4], al[4], bh[4], bl[4];
        ldsm4(sb + BHo + half * 4096 + SWZ((jt + drA + lr) * 128 + kb + dcA), ah);
        ldsm4(sb + BLo + half * 4096 + SWZ((jt + drA + lr) * 128 + kb + dcA), al);
        ldsm4t(sb + VHo + SWZ((16 * s + drA + lr) * 128 + cb2 + dcA), bh);
        ldsm4t(sb + VLo + SWZ((16 * s + drA + lr) * 128 + cb2 + dcA), bl);
        mma16816(f[0], ah, bh); mma16816(f[1], ah, bh + 2);
        mma16816(f[0], al, bh); mma16816(f[1], al, bh + 2);
        mma16816(f[0], ah, bl); mma16816(f[1], ah, bl + 2);
    }
    int q = lane & 3, g = lane >> 2;
    int cbase = (wid >> 1) * 16;
#pragma unroll
    for (int i = 0; i < 2; i++) {
        int c = cbase + i * 8 + 2 * q;
        int j = jt + g;
        *(float2*)&g_pF[(pfbase + j) * 64 + c]     = make_float2(f[i][0], f[i][1]);
        *(float2*)&g_pF[(pfbase + j + 8) * 64 + c] = make_float2(f[i][2], f[i][3]);
    }
}

// ---------------- fused fc0 + DFT --------------------------------------------
#define F0_VH 0
#define F0_VL 16384
#define F0_BH 32768
#define F0_BL 40960
#define F0_W0 49152
#define F0_SZ 50176

__global__ __launch_bounds__(256, 3)
void fc0dft_kernel(const float* __restrict__ xg, const float* __restrict__ tg,
                   const float* __restrict__ w0, const float* __restrict__ b0) {
    extern __shared__ char smc[];
    uint32_t sb = smem_u32(smc);
    float* w0s = (float*)(smc + F0_W0);
    float* b0s = w0s + 128;
    int tid = threadIdx.x, wid = tid >> 5, lane = tid & 31;
    int b = blockIdx.y, n0 = blockIdx.x * NT;

    for (int i = tid; i < 512; i += 256) {
        int half = i >> 8, rest = i & 255, j = rest >> 3, q = rest & 7;
        uint32_t so = half * 4096 + SWZ(j * 128 + q * 16);
        cpa16(sb + F0_BH + so, (const uint4*)(g_basDH + (size_t)j * NN + n0 + half * 64) + q);
        cpa16(sb + F0_BL + so, (const uint4*)(g_basDL + (size_t)j * NN + n0 + half * 64) + q);
    }
    CPA_COMMIT();
    if (tid < 128) w0s[tid] = w0[tid];
    if (tid < 64)  b0s[tid] = b0[tid];
    __syncthreads();

    int n = tid >> 1, c0 = (tid & 1) * 32;
    float xv = xg[(size_t)b * NN + n0 + n], tv = tg[(size_t)b * NN + n0 + n];
    uint32_t hw[16], lw[16];
#pragma unroll
    for (int k = 0; k < 16; k++) {
        int c = c0 + 2 * k;
        float v0 = fmaf(w0s[c],     xv, fmaf(w0s[64 + c],     tv, b0s[c]));
        float v1 = fmaf(w0s[c + 1], xv, fmaf(w0s[64 + c + 1], tv, b0s[c + 1]));
        bf16 h0, l0, h1, l1;
        split_bf(v0, h0, l0);
        split_bf(v1, h1, l1);
        hw[k] = pack_bf(h0, h1);
        lw[k] = pack_bf(l0, l1);
    }
    size_t ro = ((size_t)b * NN + n0 + n) * 64 + c0;
#pragma unroll
    for (int g4 = 0; g4 < 4; g4++) {
        uint4 hv = make_uint4(hw[4 * g4], hw[4 * g4 + 1], hw[4 * g4 + 2], hw[4 * g4 + 3]);
        uint4 lv = make_uint4(lw[4 * g4], lw[4 * g4 + 1], lw[4 * g4 + 2], lw[4 * g4 + 3]);
        *(uint4*)(g_hH0 + ro + 8 * g4) = hv;
        *(uint4*)(g_hL0 + ro + 8 * g4) = lv;
        uint32_t so = SWZ(n * 128 + c0 * 2 + g4 * 16);
        *(uint4*)(smc + F0_VH + so) = hv;
        *(uint4*)(smc + F0_VL + so) = lv;
    }
    CPA_WAIT(0);
    __syncthreads();
    dft_core8(sb, F0_VH, F0_VL, F0_BH, F0_BL, wid, lane,
              ((size_t)b * TBC + blockIdx.x) * J2);
}

// ---------------- modemix phase (shared body) --------------------------------
__device__ __forceinline__ void modemix_body(const float* fs, int tid, int b,
                                             const float* __restrict__ swr,
                                             const float* __restrict__ swi) {
    int m = tid & 15, o = tid >> 4;
    float re = 0.0f, im = 0.0f;
    for (int i = 0; i < 64; i++) {
        float fr = fs[i * 33 + 2 * m];
        float fn = fs[i * 33 + 2 * m + 1];
        float wr = swr[(i * 64 + o) * 16 + m];
        float wi = swi[(i * 64 + o) * 16 + m];
        re = fmaf(fr, wr, fmaf(fn, wi, re));
        im = fmaf(fr, wi, fmaf(-fn, wr, im));
    }
    float cm = (m == 0 ? 1.0f : 2.0f) / (float)NN;
    float g0 = cm * re;
    float g1 = -cm * im;
    size_t r = ((size_t)b * 64 + o) * 64;
    bf16 h, l;
    split_bf(g0, h, l);
    g_GpP[r + 2 * m] = h;      g_GpP[r + 32 + 2 * m] = l;
    split_bf(g1, h, l);
    g_GpP[r + 2 * m + 1] = h;  g_GpP[r + 32 + 2 * m + 1] = l;
}

// fused reduce+modemix (used for layer 0 so mma_layer is the 4th launch)
__global__ __launch_bounds__(1024)
void reduce_modemix_kernel(const float* __restrict__ swr,
                           const float* __restrict__ swi) {
    __shared__ float fs[64 * 33];   // [c][j]
    int b = blockIdx.x, tid = threadIdx.x;
    for (int idx = tid; idx < 2048; idx += 1024) {
        int j = idx >> 6, c = idx & 63;
        float s = 0.0f;
        const float* p = &g_pF[(size_t)b * TBC * 2048 + idx];
#pragma unroll 8
        for (int ch = 0; ch < TBC; ch++) s += p[(size_t)ch * 2048];
        fs[c * 33 + j] = s;
    }
    __syncthreads();
    modemix_body(fs, tid, b, swr, swi);
}

__global__ __launch_bounds__(256)
void reduce_kernel() {
    int b = blockIdx.x;
    int idx = blockIdx.y * 256 + threadIdx.x;
    const float* p = &g_pF[(size_t)b * TBC * 2048 + idx];
    float s = 0.0f;
#pragma unroll 8
    for (int ch = 0; ch < TBC; ch++) s += p[(size_t)ch * 2048];
    g_F[(size_t)b * 2048 + idx] = s;
}

__global__ __launch_bounds__(1024)
void modemix_kernel(const float* __restrict__ swr,
                    const float* __restrict__ swi) {
    __shared__ float fs[64 * 33];   // [c][j]
    int b = blockIdx.x, tid = threadIdx.x;
    for (int idx = tid; idx < 2048; idx += 1024) {
        int j = idx >> 6, c = idx & 63;
        fs[c * 33 + j] = g_F[(size_t)b * 2048 + idx];
    }
    __syncthreads();
    modemix_body(fs, tid, b, swr, swi);
}

// ---------------- shared smem layout for layer kernels -----------------------
#define MM_HH  0
#define MM_HL  16384
#define MM_WH  32768
#define MM_WL  40960
#define MM_BDH 49152
#define MM_BDL 57344
#define MM_G   65536
#define MM_CB  73728
#define MM_SZ  73984
#define M3_B1  73728
#define M3_W2  74240
#define M3_CB  74752
#define M3_SZ  75008

__device__ __forceinline__ void layer_gemm(uint32_t sb, int wid, int lane, float acc[8][4]) {
    int lr = lane & 7, li = lane >> 3;
    int drA = (li & 1) * 8, dcA = (li >> 1) * 16;
    int drB = (li >> 1) * 8, dcB = (li & 1) * 16;
    int rA0 = 16 * wid;

#pragma unroll
    for (int s = 0; s < 4; s++) {
        int kb = s * 32;
        uint32_t ah[4], al[4];
        ldsm4(sb + MM_HH + SWZ((rA0 + drA + lr) * 128 + kb + dcA), ah);
        ldsm4(sb + MM_HL + SWZ((rA0 + drA + lr) * 128 + kb + dcA), al);
#pragma unroll
        for (int np = 0; np < 4; np++) {
            uint32_t bb[4];
            ldsm4(sb + MM_WH + SWZ((np * 16 + drB + lr) * 128 + kb + dcB), bb);
            mma16816(acc[2 * np],     ah, bb);
            mma16816(acc[2 * np + 1], ah, bb + 2);
            mma16816(acc[2 * np],     al, bb);
            mma16816(acc[2 * np + 1], al, bb + 2);
            ldsm4(sb + MM_WL + SWZ((np * 16 + drB + lr) * 128 + kb + dcB), bb);
            mma16816(acc[2 * np],     ah, bb);
            mma16816(acc[2 * np + 1], ah, bb + 2);
        }
    }
    CPA_WAIT(0);
    __syncthreads();

    {
        int halfS = rA0 >> 6;
        int colA = (rA0 & 63) * 2 + (li & 1) * 16;
        int rowA = (li >> 1) * 8 + lr;
#pragma unroll
        for (int s = 0; s < 2; s++) {
            int kb = s * 32;
            uint32_t ah[4], al[4];
            ldsm4t(sb + MM_BDH + halfS * 4096 + SWZ((s * 16 + rowA) * 128 + colA), ah);
            ldsm4t(sb + MM_BDL + halfS * 4096 + SWZ((s * 16 + rowA) * 128 + colA), al);
#pragma unroll
            for (int np = 0; np < 4; np++) {
                uint32_t bb[4];
                ldsm4(sb + MM_G + SWZ((np * 16 + drB + lr) * 128 + kb + dcB), bb);
                mma16816(acc[2 * np],     ah, bb);
                mma16816(acc[2 * np + 1], ah, bb + 2);
                mma16816(acc[2 * np],     al, bb);
                mma16816(acc[2 * np + 1], al, bb + 2);
                ldsm4(sb + MM_G + SWZ((np * 16 + drB + lr) * 128 + 64 + kb + dcB), bb);
                mma16816(acc[2 * np],     ah, bb);
                mma16816(acc[2 * np + 1], ah, bb + 2);
            }
        }
    }
}

__device__ __forceinline__ void layer_loads(uint32_t sb, int tid, int layer, int b, int n0,
                                            const bf16* hHsrc, const bf16* hLsrc) {
    for (int i = tid; i < 1024; i += 256) {
        int r = i >> 3, q = i & 7;
        uint32_t so = SWZ(r * 128 + q * 16);
        cpa16(sb + MM_HH + so, (const uint4*)(hHsrc + (size_t)r * 64) + q);
        cpa16(sb + MM_HL + so, (const uint4*)(hLsrc + (size_t)r * 64) + q);
    }
    for (int i = tid; i < 512; i += 256) {
        int r = i >> 3, q = i & 7;
        uint32_t so = SWZ(r * 128 + q * 16);
        cpa16(sb + MM_WH + so, (const uint4*)(g_cwH + (size_t)(layer * 64 + r) * 64) + q);
        cpa16(sb + MM_WL + so, (const uint4*)(g_cwL + (size_t)(layer * 64 + r) * 64) + q);
    }
    CPA_COMMIT();
    for (int i = tid; i < 512; i += 256) {
        int r = i >> 3, q = i & 7;
        uint32_t so = SWZ(r * 128 + q * 16);
        cpa16(sb + MM_G + so, (const uint4*)(g_GpP + ((size_t)b * 64 + r) * 64) + q);
        int half = i >> 8, rest = i & 255, j = rest >> 3, qq = rest & 7;
        uint32_t so2 = half * 4096 + SWZ(j * 128 + qq * 16);
        cpa16(sb + MM_BDH + so2, (const uint4*)(g_basDH + (size_t)j * NN + n0 + half * 64) + qq);
        cpa16(sb + MM_BDL + so2, (const uint4*)(g_basDL + (size_t)j * NN + n0 + half * 64) + qq);
    }
    CPA_COMMIT();
}

// ---------------- fused layer 0-2: conv + synthesis + gelu + DFT --------------
__global__ __launch_bounds__(256, 3)
void mma_layer(int dir, int layer, int rev, const float* __restrict__ cb_all) {
    extern __shared__ char smc[];
    uint32_t sb = smem_u32(smc);
    int tid = threadIdx.x, wid = tid >> 5, lane = tid & 31;
    int b   = rev ? (BB - 1 - (int)blockIdx.y) : (int)blockIdx.y;
    int chk = rev ? (TBC - 1 - (int)blockIdx.x) : (int)blockIdx.x;
    int n0 = chk * NT;

    const bf16* hHsrc = (dir ? g_hH1 : g_hH0) + ((size_t)b * NN + n0) * 64;
    const bf16* hLsrc = (dir ? g_hL1 : g_hL0) + ((size_t)b * NN + n0) * 64;
    bf16* hHdst = (dir ? g_hH0 : g_hH1) + ((size_t)b * NN + n0) * 64;
    bf16* hLdst = (dir ? g_hL0 : g_hL1) + ((size_t)b * NN + n0) * 64;

    layer_loads(sb, tid, layer, b, n0, hHsrc, hLsrc);
    if (tid < 64) ((float*)(smc + MM_CB))[tid] = cb_all[layer * 64 + tid];
    CPA_WAIT(1);
    __syncthreads();

    float acc[8][4];
#pragma unroll
    for (int nt = 0; nt < 8; nt++)
#pragma unroll
        for (int k = 0; k < 4; k++) acc[nt][k] = 0.0f;

    layer_gemm(sb, wid, lane, acc);
    __syncthreads();

    int q = lane & 3, g = lane >> 2;
    const float* cbs = (const float*)(smc + MM_CB);
#pragma unroll
    for (int nt = 0; nt < 8; nt++) {
        int o0 = nt * 8 + 2 * q;
        int r0 = 16 * wid + g;
        float v0 = gelu_exact(acc[nt][0] + cbs[o0]);
        float v1 = gelu_exact(acc[nt][1] + cbs[o0 + 1]);
        float v2 = gelu_exact(acc[nt][2] + cbs[o0]);
        float v3 = gelu_exact(acc[nt][3] + cbs[o0 + 1]);
        bf16 h0, l0, h1, l1;
        split_bf(v0, h0, l0); split_bf(v1, h1, l1);
        *(uint32_t*)(smc + MM_HH + SWZ(r0 * 128 + o0 * 2)) = pack_bf(h0, h1);
        *(uint32_t*)(smc + MM_HL + SWZ(r0 * 128 + o0 * 2)) = pack_bf(l0, l1);
        split_bf(v2, h0, l0); split_bf(v3, h1, l1);
        *(uint32_t*)(smc + MM_HH + SWZ((r0 + 8) * 128 + o0 * 2)) = pack_bf(h0, h1);
        *(uint32_t*)(smc + MM_HL + SWZ((r0 + 8) * 128 + o0 * 2)) = pack_bf(l0, l1);
    }
    __syncthreads();

    // DFT first (tensor work resumes immediately); copy-out drains afterwards
    dft_core8(sb, MM_HH, MM_HL, MM_BDH, MM_BDL, wid, lane,
              ((size_t)b * TBC + chk) * J2);

    for (int i = tid; i < 1024; i += 256) {
        int r = i >> 3, qq = i & 7;
        uint32_t so = SWZ(r * 128 + qq * 16);
        ((uint4*)(hHdst + (size_t)r * 64))[qq] = *(uint4*)(smc + MM_HH + so);
        ((uint4*)(hLdst + (size_t)r * 64))[qq] = *(uint4*)(smc + MM_HL + so);
    }
}

// ---------------- fused layer 3 + fc1 + gelu + fc2 ---------------------------
__global__ __launch_bounds__(256, 3)
void mma_layer3fc(const float* __restrict__ cb_all,
                  const float* __restrict__ b1, const float* __restrict__ w2,
                  const float* __restrict__ b2, float* __restrict__ out) {
    extern __shared__ char smc[];
    uint32_t sb = smem_u32(smc);
    int tid = threadIdx.x, wid = tid >> 5, lane = tid & 31;
    int b = blockIdx.y, n0 = blockIdx.x * NT;   // forward (layer 2 ran reversed)

    const bf16* hHsrc = g_hH1 + ((size_t)b * NN + n0) * 64;
    const bf16* hLsrc = g_hL1 + ((size_t)b * NN + n0) * 64;

    layer_loads(sb, tid, 3, b, n0, hHsrc, hLsrc);
    if (tid < 64)  ((float*)(smc + M3_CB))[tid] = cb_all[3 * 64 + tid];
    if (tid < 128) {
        ((float*)(smc + M3_B1))[tid] = b1[tid];
        ((float*)(smc + M3_W2))[tid] = w2[tid];
    }
    CPA_WAIT(1);
    __syncthreads();

    float acc[8][4];
#pragma unroll
    for (int nt = 0; nt < 8; nt++)
#pragma unroll
        for (int k = 0; k < 4; k++) acc[nt][k] = 0.0f;

    layer_gemm(sb, wid, lane, acc);
    __syncthreads();   // weight/basis regions now dead

    // prefetch w1 into dead regions [32768, 65536)
    for (int i = tid; i < 2048; i += 256) {
        int buf = i >> 10, rest = i & 1023, r = rest >> 3, q = rest & 7;
        uint32_t so = SWZ(r * 128 + q * 16);
        const bf16* src = buf ? g_w1TL : g_w1TH;
        cpa16(sb + 32768 + buf * 16384 + so, (const uint4*)(src + (size_t)r * 64) + q);
    }
    CPA_COMMIT();

    // epilogue: v = acc + cb (no gelu), split into HH/HL
    int q = lane & 3, g = lane >> 2;
    const float* cbs = (const float*)(smc + M3_CB);
#pragma unroll
    for (int nt = 0; nt < 8; nt++) {
        int o0 = nt * 8 + 2 * q;
        int r0 = 16 * wid + g;
        float v0 = acc[nt][0] + cbs[o0];
        float v1 = acc[nt][1] + cbs[o0 + 1];
        float v2 = acc[nt][2] + cbs[o0];
        float v3 = acc[nt][3] + cbs[o0 + 1];
        bf16 h0, l0, h1, l1;
        split_bf(v0, h0, l0); split_bf(v1, h1, l1);
        *(uint32_t*)(smc + MM_HH + SWZ(r0 * 128 + o0 * 2)) = pack_bf(h0, h1);
        *(uint32_t*)(smc + MM_HL + SWZ(r0 * 128 + o0 * 2)) = pack_bf(l0, l1);
        split_bf(v2, h0, l0); split_bf(v3, h1, l1);
        *(uint32_t*)(smc + MM_HH + SWZ((r0 + 8) * 128 + o0 * 2)) = pack_bf(h0, h1);
        *(uint32_t*)(smc + MM_HL + SWZ((r0 + 8) * 128 + o0 * 2)) = pack_bf(l0, l1);
    }
    CPA_WAIT(0);
    __syncthreads();

    // fc1 in two j-halves (register-lean) + gelu·w2 fold
    int lr = lane & 7, li = lane >> 3;
    int drA = (li & 1) * 8, dcA = (li >> 1) * 16;
    int drB = (li >> 1) * 8, dcB = (li & 1) * 16;
    int rA0 = 16 * wid;
    const uint32_t W1H = sb + 32768, W1L = sb + 49152;
    const float* b1s = (const float*)(smc + M3_B1);
    const float* w2s = (const float*)(smc + M3_W2);

    float s0 = 0.0f, s1 = 0.0f;
#pragma unroll
    for (int half = 0; half < 2; half++) {
        float fac[8][4];
#pragma unroll
        for (int nt = 0; nt < 8; nt++)
#pragma unroll
            for (int k = 0; k < 4; k++) fac[nt][k] = 0.0f;

#pragma unroll
        for (int s = 0; s < 4; s++) {
            int kb = s * 32;
            uint32_t ah[4], al[4];
            ldsm4(sb + MM_HH + SWZ((rA0 + drA + lr) * 128 + kb + dcA), ah);
            ldsm4(sb + MM_HL + SWZ((rA0 + drA + lr) * 128 + kb + dcA), al);
#pragma unroll
            for (int np = 0; np < 4; np++) {
                int npp = half * 4 + np;
                uint32_t bb[4];
                ldsm4(W1H + SWZ((npp * 16 + drB + lr) * 128 + kb + dcB), bb);
                mma16816(fac[2 * np],     ah, bb);
                mma16816(fac[2 * np + 1], ah, bb + 2);
                mma16816(fac[2 * np],     al, bb);
                mma16816(fac[2 * np + 1], al, bb + 2);
                ldsm4(W1L + SWZ((npp * 16 + drB + lr) * 128 + kb + dcB), bb);
                mma16816(fac[2 * np],     ah, bb);
                mma16816(fac[2 * np + 1], ah, bb + 2);
            }
        }
#pragma unroll
        for (int nt = 0; nt < 8; nt++) {
            int j0 = half * 64 + nt * 8 + 2 * q;
            s0 = fmaf(w2s[j0],     gelu_exact(fac[nt][0] + b1s[j0]),     s0);
            s0 = fmaf(w2s[j0 + 1], gelu_exact(fac[nt][1] + b1s[j0 + 1]), s0);
            s1 = fmaf(w2s[j0],     gelu_exact(fac[nt][2] + b1s[j0]),     s1);
            s1 = fmaf(w2s[j0 + 1], gelu_exact(fac[nt][3] + b1s[j0 + 1]), s1);
        }
    }
    s0 += __shfl_xor_sync(0xffffffffu, s0, 1);
    s0 += __shfl_xor_sync(0xffffffffu, s0, 2);
    s1 += __shfl_xor_sync(0xffffffffu, s1, 1);
    s1 += __shfl_xor_sync(0xffffffffu, s1, 2);
    if (q == 0) {
        float bv = b2[0];
        out[(size_t)b * NN + n0 + 16 * wid + g]     = s0 + bv;
        out[(size_t)b * NN + n0 + 16 * wid + g + 8] = s1 + bv;
    }
}

// ---------------- host launcher ----------------------------------------------
extern "C" void kernel_launch(void* const* d_in, const int* in_sizes, int n_in,
                              void* d_out, int out_size) {
    const float* x    = (const float*)d_in[0];
    const float* t    = (const float*)d_in[1];
    const float* fc0w = (const float*)d_in[2];
    const float* fc0b = (const float*)d_in[3];
    const float* swr  = (const float*)d_in[4];
    const float* swi  = (const float*)d_in[5];
    const float* cw   = (const float*)d_in[6];
    const float* cb   = (const float*)d_in[7];
    const float* w1   = (const float*)d_in[8];
    const float* b1   = (const float*)d_in[9];
    const float* w2   = (const float*)d_in[10];
    const float* b2   = (const float*)d_in[11];
    float* out = (float*)d_out;

    cudaFuncSetAttribute(mma_layer,    cudaFuncAttributeMaxDynamicSharedMemorySize, MM_SZ);
    cudaFuncSetAttribute(mma_layer3fc, cudaFuncAttributeMaxDynamicSharedMemorySize, M3_SZ);
    cudaFuncSetAttribute(fc0dft_kernel, cudaFuncAttributeMaxDynamicSharedMemorySize, F0_SZ);

    dim3 g(TBC, BB);
    dim3 gr(BB, 8);
    // launch order: prep(1), fc0dft(2), rmm(3), mma_layer(4 <- ncu sample slot)
    prep_all<<<(NN + 4 * 4096 + 128 * 64 + 255) / 256, 256>>>(cw, w1);

    fc0dft_kernel<<<g, 256, F0_SZ>>>(x, t, fc0w, fc0b);      // forward

    const size_t SWL = (size_t)64 * 64 * 16;
    reduce_modemix_kernel<<<BB, 1024>>>(swr + 0 * SWL, swi + 0 * SWL);
    mma_layer<<<g, 256, MM_SZ>>>(0, 0, 1, cb);               // reversed

    reduce_kernel<<<gr, 256>>>();
    modemix_kernel<<<BB, 1024>>>(swr + 1 * SWL, swi + 1 * SWL);
    mma_layer<<<g, 256, MM_SZ>>>(1, 1, 0, cb);               // forward

    reduce_kernel<<<gr, 256>>>();
    modemix_kernel<<<BB, 1024>>>(swr + 2 * SWL, swi + 2 * SWL);
    mma_layer<<<g, 256, MM_SZ>>>(0, 2, 1, cb);               // reversed

    reduce_kernel<<<gr, 256>>>();
    modemix_kernel<<<BB, 1024>>>(swr + 3 * SWL, swi + 3 * SWL);
    mma_layer3fc<<<g, 256, M3_SZ>>>(cb, b1, w2, b2, out);    // forward, fused
}

// round 17
// speedup vs baseline: 1.1169x; 1.0053x over previous
#include <cuda_runtime.h>
#include <cuda_bf16.h>
#include <math.h>
#include <stdint.h>
#include <stddef.h>

#define BB 64
#define NN 8192
#define MODES 16
#define J2 32
#define NT 128
#define TBC (NN / NT)

typedef __nv_bfloat16 bf16;

// ---------------- device scratch --------------------------------------------
__device__ bf16  g_hH0[(size_t)BB * NN * 64];
__device__ bf16  g_hL0[(size_t)BB * NN * 64];
__device__ bf16  g_hH1[(size_t)BB * NN * 64];
__device__ bf16  g_hL1[(size_t)BB * NN * 64];
__device__ float g_pF[(size_t)BB * TBC * J2 * 64];    // [b][chunk][j][c]
__device__ float g_F[(size_t)BB * J2 * 64];           // [b][j][c]
__device__ bf16  g_basDH[(size_t)J2 * NN];            // [j][n] hi
__device__ bf16  g_basDL[(size_t)J2 * NN];            // [j][n] lo
__device__ bf16  g_cwH[4 * 64 * 64];                  // [l][o][c]
__device__ bf16  g_cwL[4 * 64 * 64];
__device__ bf16  g_GpP[(size_t)BB * 64 * 64];         // [b][o][ gh(32) | gl(32) ]
__device__ bf16  g_w1TH[128 * 64];                    // [j][c]
__device__ bf16  g_w1TL[128 * 64];

// ---------------- helpers ----------------------------------------------------
#define SWZ(x) ((x) ^ (((x) >> 3) & 0x70))

__device__ __forceinline__ uint32_t smem_u32(const void* p) {
    uint32_t a;
    asm("{ .reg .u64 t; cvta.to.shared.u64 t, %1; cvt.u32.u64 %0, t; }" : "=r"(a) : "l"(p));
    return a;
}
__device__ __forceinline__ void cpa16(uint32_t dst, const void* src) {
    asm volatile("cp.async.cg.shared.global [%0], [%1], 16;" :: "r"(dst), "l"(src));
}
#define CPA_COMMIT() asm volatile("cp.async.commit_group;" ::: "memory")
#define CPA_WAIT(n)  asm volatile("cp.async.wait_group %0;" :: "n"(n) : "memory")

__device__ __forceinline__ void ldsm4(uint32_t a, uint32_t* r) {
    asm volatile("ldmatrix.sync.aligned.m8n8.x4.shared.b16 {%0,%1,%2,%3}, [%4];"
                 : "=r"(r[0]), "=r"(r[1]), "=r"(r[2]), "=r"(r[3]) : "r"(a));
}
__device__ __forceinline__ void ldsm4t(uint32_t a, uint32_t* r) {
    asm volatile("ldmatrix.sync.aligned.m8n8.x4.trans.shared.b16 {%0,%1,%2,%3}, [%4];"
                 : "=r"(r[0]), "=r"(r[1]), "=r"(r[2]), "=r"(r[3]) : "r"(a));
}
__device__ __forceinline__ void mma16816(float* d, const uint32_t* a, const uint32_t* b) {
    asm volatile(
        "mma.sync.aligned.m16n8k16.row.col.f32.bf16.bf16.f32 "
        "{%0,%1,%2,%3},{%4,%5,%6,%7},{%8,%9},{%0,%1,%2,%3};"
        : "+f"(d[0]), "+f"(d[1]), "+f"(d[2]), "+f"(d[3])
        : "r"(a[0]), "r"(a[1]), "r"(a[2]), "r"(a[3]), "r"(b[0]), "r"(b[1]));
}
__device__ __forceinline__ float gelu_exact(float v) {
    return 0.5f * v * (1.0f + erff(v * 0.70710678118654752f));
}
__device__ __forceinline__ void split_bf(float v, bf16& h, bf16& l) {
    h = __float2bfloat16(v);
    l = __float2bfloat16(v - __bfloat162float(h));
}
__device__ __forceinline__ uint32_t pack_bf(bf16 a, bf16 b) {
    return (uint32_t)__bfloat16_as_ushort(a) | ((uint32_t)__bfloat16_as_ushort(b) << 16);
}

// ---------------- merged prep (one launch) -----------------------------------
__global__ void prep_all(const float* __restrict__ cw, const float* __restrict__ w1) {
    int gidx = blockIdx.x * 256 + threadIdx.x;
    if (gidx < NN) {
        int n = gidx;
#pragma unroll
        for (int m = 0; m < MODES; m++) {
            int r = (m * n) & (NN - 1);
            float tf = 2.0f * (float)r / (float)NN;
            float s, c;
            sincospif(tf, &s, &c);
            bf16 h, l;
            split_bf(c, h, l);
            g_basDH[(size_t)(2 * m) * NN + n] = h;
            g_basDL[(size_t)(2 * m) * NN + n] = l;
            split_bf(s, h, l);
            g_basDH[(size_t)(2 * m + 1) * NN + n] = h;
            g_basDL[(size_t)(2 * m + 1) * NN + n] = l;
        }
    } else if (gidx < NN + 4 * 64 * 64) {
        int idx = gidx - NN;
        bf16 h, l;
        split_bf(cw[idx], h, l);
        g_cwH[idx] = h; g_cwL[idx] = l;
    } else if (gidx < NN + 4 * 64 * 64 + 128 * 64) {
        int i2 = gidx - NN - 4 * 64 * 64;
        int c = i2 >> 7, j = i2 & 127;
        bf16 h, l;
        split_bf(w1[c * 128 + j], h, l);
        g_w1TH[j * 64 + c] = h; g_w1TL[j * 64 + c] = l;
    }
}

// ---------------- DFT MMA core (8 warps) -------------------------------------
__device__ __forceinline__ void dft_core8(uint32_t sb, int VHo, int VLo, int BHo, int BLo,
                                          int wid, int lane, size_t pfbase) {
    int lr = lane & 7, li = lane >> 3;
    int drA = (li & 1) * 8, dcA = (li >> 1) * 16;
    int jt = (wid & 1) * 16;
    int cb2 = (wid >> 1) * 32;
    float f[2][4];
#pragma unroll
    for (int i = 0; i < 2; i++)
#pragma unroll
        for (int k = 0; k < 4; k++) f[i][k] = 0.0f;

#pragma unroll
    for (int s = 0; s < 8; s++) {
        int half = s >> 2, kb = (s & 3) * 32;
        uint32_t ah[4], al[4], bh[4], bl[4];
        ldsm4(sb + BHo + half * 4096 + SWZ((jt + drA + lr) * 128 + kb + dcA), ah);
        ldsm4(sb + BLo + half * 4096 + SWZ((jt + drA + lr) * 128 + kb + dcA), al);
        ldsm4t(sb + VHo + SWZ((16 * s + drA + lr) * 128 + cb2 + dcA), bh);
        ldsm4t(sb + VLo + SWZ((16 * s + drA + lr) * 128 + cb2 + dcA), bl);
        mma16816(f[0], ah, bh); mma16816(f[1], ah, bh + 2);
        mma16816(f[0], al, bh); mma16816(f[1], al, bh + 2);
        mma16816(f[0], ah, bl); mma16816(f[1], ah, bl + 2);
    }
    int q = lane & 3, g = lane >> 2;
    int cbase = (wid >> 1) * 16;
#pragma unroll
    for (int i = 0; i < 2; i++) {
        int c = cbase + i * 8 + 2 * q;
        int j = jt + g;
        *(float2*)&g_pF[(pfbase + j) * 64 + c]     = make_float2(f[i][0], f[i][1]);
        *(float2*)&g_pF[(pfbase + j + 8) * 64 + c] = make_float2(f[i][2], f[i][3]);
    }
}

// ---------------- fused fc0 + DFT --------------------------------------------
#define F0_VH 0
#define F0_VL 16384
#define F0_BH 32768
#define F0_BL 40960
#define F0_W0 49152
#define F0_SZ 50176

__global__ __launch_bounds__(256, 3)
void fc0dft_kernel(const float* __restrict__ xg, const float* __restrict__ tg,
                   const float* __restrict__ w0, const float* __restrict__ b0) {
    extern __shared__ char smc[];
    uint32_t sb = smem_u32(smc);
    float* w0s = (float*)(smc + F0_W0);
    float* b0s = w0s + 128;
    int tid = threadIdx.x, wid = tid >> 5, lane = tid & 31;
    int b = blockIdx.y, n0 = blockIdx.x * NT;

    for (int i = tid; i < 512; i += 256) {
        int half = i >> 8, rest = i & 255, j = rest >> 3, q = rest & 7;
        uint32_t so = half * 4096 + SWZ(j * 128 + q * 16);
        cpa16(sb + F0_BH + so, (const uint4*)(g_basDH + (size_t)j * NN + n0 + half * 64) + q);
        cpa16(sb + F0_BL + so, (const uint4*)(g_basDL + (size_t)j * NN + n0 + half * 64) + q);
    }
    CPA_COMMIT();
    if (tid < 128) w0s[tid] = w0[tid];
    if (tid < 64)  b0s[tid] = b0[tid];
    __syncthreads();

    int n = tid >> 1, c0 = (tid & 1) * 32;
    float xv = xg[(size_t)b * NN + n0 + n], tv = tg[(size_t)b * NN + n0 + n];
    uint32_t hw[16], lw[16];
#pragma unroll
    for (int k = 0; k < 16; k++) {
        int c = c0 + 2 * k;
        float v0 = fmaf(w0s[c],     xv, fmaf(w0s[64 + c],     tv, b0s[c]));
        float v1 = fmaf(w0s[c + 1], xv, fmaf(w0s[64 + c + 1], tv, b0s[c + 1]));
        bf16 h0, l0, h1, l1;
        split_bf(v0, h0, l0);
        split_bf(v1, h1, l1);
        hw[k] = pack_bf(h0, h1);
        lw[k] = pack_bf(l0, l1);
    }
    size_t ro = ((size_t)b * NN + n0 + n) * 64 + c0;
#pragma unroll
    for (int g4 = 0; g4 < 4; g4++) {
        uint4 hv = make_uint4(hw[4 * g4], hw[4 * g4 + 1], hw[4 * g4 + 2], hw[4 * g4 + 3]);
        uint4 lv = make_uint4(lw[4 * g4], lw[4 * g4 + 1], lw[4 * g4 + 2], lw[4 * g4 + 3]);
        *(uint4*)(g_hH0 + ro + 8 * g4) = hv;
        *(uint4*)(g_hL0 + ro + 8 * g4) = lv;
        uint32_t so = SWZ(n * 128 + c0 * 2 + g4 * 16);
        *(uint4*)(smc + F0_VH + so) = hv;
        *(uint4*)(smc + F0_VL + so) = lv;
    }
    CPA_WAIT(0);
    __syncthreads();
    dft_core8(sb, F0_VH, F0_VL, F0_BH, F0_BL, wid, lane,
              ((size_t)b * TBC + blockIdx.x) * J2);
}

// ---------------- modemix phase (shared body) --------------------------------
__device__ __forceinline__ void modemix_body(const float* fs, int tid, int b,
                                             const float* __restrict__ swr,
                                             const float* __restrict__ swi) {
    int m = tid & 15, o = tid >> 4;
    float re = 0.0f, im = 0.0f;
    for (int i = 0; i < 64; i++) {
        float fr = fs[i * 33 + 2 * m];
        float fn = fs[i * 33 + 2 * m + 1];
        float wr = swr[(i * 64 + o) * 16 + m];
        float wi = swi[(i * 64 + o) * 16 + m];
        re = fmaf(fr, wr, fmaf(fn, wi, re));
        im = fmaf(fr, wi, fmaf(-fn, wr, im));
    }
    float cm = (m == 0 ? 1.0f : 2.0f) / (float)NN;
    float g0 = cm * re;
    float g1 = -cm * im;
    size_t r = ((size_t)b * 64 + o) * 64;
    bf16 h, l;
    split_bf(g0, h, l);
    g_GpP[r + 2 * m] = h;      g_GpP[r + 32 + 2 * m] = l;
    split_bf(g1, h, l);
    g_GpP[r + 2 * m + 1] = h;  g_GpP[r + 32 + 2 * m + 1] = l;
}

__global__ __launch_bounds__(1024)
void reduce_modemix_kernel(const float* __restrict__ swr,
                           const float* __restrict__ swi) {
    __shared__ float fs[64 * 33];   // [c][j]
    int b = blockIdx.x, tid = threadIdx.x;
    for (int idx = tid; idx < 2048; idx += 1024) {
        int j = idx >> 6, c = idx & 63;
        float s = 0.0f;
        const float* p = &g_pF[(size_t)b * TBC * 2048 + idx];
#pragma unroll 8
        for (int ch = 0; ch < TBC; ch++) s += p[(size_t)ch * 2048];
        fs[c * 33 + j] = s;
    }
    __syncthreads();
    modemix_body(fs, tid, b, swr, swi);
}

__global__ __launch_bounds__(256)
void reduce_kernel() {
    int b = blockIdx.x;
    int idx = blockIdx.y * 256 + threadIdx.x;
    const float* p = &g_pF[(size_t)b * TBC * 2048 + idx];
    float s = 0.0f;
#pragma unroll 8
    for (int ch = 0; ch < TBC; ch++) s += p[(size_t)ch * 2048];
    g_F[(size_t)b * 2048 + idx] = s;
}

__global__ __launch_bounds__(1024)
void modemix_kernel(const float* __restrict__ swr,
                    const float* __restrict__ swi) {
    __shared__ float fs[64 * 33];   // [c][j]
    int b = blockIdx.x, tid = threadIdx.x;
    for (int idx = tid; idx < 2048; idx += 1024) {
        int j = idx >> 6, c = idx & 63;
        fs[c * 33 + j] = g_F[(size_t)b * 2048 + idx];
    }
    __syncthreads();
    modemix_body(fs, tid, b, swr, swi);
}

// ---------------- shared smem layout for layer kernels -----------------------
#define MM_HH  0
#define MM_HL  16384
#define MM_WH  32768
#define MM_WL  40960
#define MM_BDH 49152
#define MM_BDL 57344
#define MM_G   65536
#define MM_CB  73728
#define MM_SZ  73984
#define M3_B1  73728
#define M3_W2  74240
#define M3_CB  74752
#define M3_SZ  75008

// GEMM body, 32n x 32o warp tile: wy = wid&3 (rows), wx = wid>>2 (cols).
// acc[rt][cc][4]: rt = row-tile (16 rows), cc = np*2 + n8half.
__device__ __forceinline__ void layer_gemm(uint32_t sb, int wy, int wx, int lane,
                                           float acc[2][4][4]) {
    int lr = lane & 7, li = lane >> 3;
    int drA = (li & 1) * 8, dcA = (li >> 1) * 16;
    int drB = (li >> 1) * 8, dcB = (li & 1) * 16;
    int rA0 = 32 * wy;
    int oB0 = 32 * wx;                 // o index base

    // conv: (Hh+Hl)(Wh+Wl) 3-term
#pragma unroll
    for (int s = 0; s < 4; s++) {
        int kb = s * 32;
        uint32_t ah0[4], al0[4], ah1[4], al1[4];
        ldsm4(sb + MM_HH + SWZ((rA0 + drA + lr) * 128 + kb + dcA), ah0);
        ldsm4(sb + MM_HL + SWZ((rA0 + drA + lr) * 128 + kb + dcA), al0);
        ldsm4(sb + MM_HH + SWZ((rA0 + 16 + drA + lr) * 128 + kb + dcA), ah1);
        ldsm4(sb + MM_HL + SWZ((rA0 + 16 + drA + lr) * 128 + kb + dcA), al1);
#pragma unroll
        for (int np = 0; np < 2; np++) {
            uint32_t bb[4];
            ldsm4(sb + MM_WH + SWZ((oB0 + np * 16 + drB + lr) * 128 + kb + dcB), bb);
            mma16816(acc[0][2 * np],     ah0, bb);
            mma16816(acc[0][2 * np + 1], ah0, bb + 2);
            mma16816(acc[0][2 * np],     al0, bb);
            mma16816(acc[0][2 * np + 1], al0, bb + 2);
            mma16816(acc[1][2 * np],     ah1, bb);
            mma16816(acc[1][2 * np + 1], ah1, bb + 2);
            mma16816(acc[1][2 * np],     al1, bb);
            mma16816(acc[1][2 * np + 1], al1, bb + 2);
            ldsm4(sb + MM_WL + SWZ((oB0 + np * 16 + drB + lr) * 128 + kb + dcB), bb);
            mma16816(acc[0][2 * np],     ah0, bb);
            mma16816(acc[0][2 * np + 1], ah0, bb + 2);
            mma16816(acc[1][2 * np],     ah1, bb);
            mma16816(acc[1][2 * np + 1], ah1, bb + 2);
        }
    }
    CPA_WAIT(0);
    __syncthreads();

    // synthesis: A = trans(basD half tile), B = packed G (gh bytes 0-63, gl 64-127)
    {
        int halfS = rA0 >> 6;
        int colA0 = (rA0 & 63) * 2 + (li & 1) * 16;
        int rowA = (li >> 1) * 8 + lr;
#pragma unroll
        for (int s = 0; s < 2; s++) {
            int kb = s * 32;
            uint32_t ah0[4], al0[4], ah1[4], al1[4];
            ldsm4t(sb + MM_BDH + halfS * 4096 + SWZ((s * 16 + rowA) * 128 + colA0), ah0);
            ldsm4t(sb + MM_BDL + halfS * 4096 + SWZ((s * 16 + rowA) * 128 + colA0), al0);
            ldsm4t(sb + MM_BDH + halfS * 4096 + SWZ((s * 16 + rowA) * 128 + colA0 + 32), ah1);
            ldsm4t(sb + MM_BDL + halfS * 4096 + SWZ((s * 16 + rowA) * 128 + colA0 + 32), al1);
#pragma unroll
            for (int np = 0; np < 2; np++) {
                uint32_t bb[4];
                ldsm4(sb + MM_G + SWZ((oB0 + np * 16 + drB + lr) * 128 + kb + dcB), bb);
                mma16816(acc[0][2 * np],     ah0, bb);
                mma16816(acc[0][2 * np + 1], ah0, bb + 2);
                mma16816(acc[0][2 * np],     al0, bb);
                mma16816(acc[0][2 * np + 1], al0, bb + 2);
                mma16816(acc[1][2 * np],     ah1, bb);
                mma16816(acc[1][2 * np + 1], ah1, bb + 2);
                mma16816(acc[1][2 * np],     al1, bb);
                mma16816(acc[1][2 * np + 1], al1, bb + 2);
                ldsm4(sb + MM_G + SWZ((oB0 + np * 16 + drB + lr) * 128 + 64 + kb + dcB), bb);
                mma16816(acc[0][2 * np],     ah0, bb);
                mma16816(acc[0][2 * np + 1], ah0, bb + 2);
                mma16816(acc[1][2 * np],     ah1, bb);
                mma16816(acc[1][2 * np + 1], ah1, bb + 2);
            }
        }
    }
}

__device__ __forceinline__ void layer_loads(uint32_t sb, int tid, int layer, int b, int n0,
                                            const bf16* hHsrc, const bf16* hLsrc) {
    for (int i = tid; i < 1024; i += 256) {
        int r = i >> 3, q = i & 7;
        uint32_t so = SWZ(r * 128 + q * 16);
        cpa16(sb + MM_HH + so, (const uint4*)(hHsrc + (size_t)r * 64) + q);
        cpa16(sb + MM_HL + so, (const uint4*)(hLsrc + (size_t)r * 64) + q);
    }
    for (int i = tid; i < 512; i += 256) {
        int r = i >> 3, q = i & 7;
        uint32_t so = SWZ(r * 128 + q * 16);
        cpa16(sb + MM_WH + so, (const uint4*)(g_cwH + (size_t)(layer * 64 + r) * 64) + q);
        cpa16(sb + MM_WL + so, (const uint4*)(g_cwL + (size_t)(layer * 64 + r) * 64) + q);
    }
    CPA_COMMIT();
    for (int i = tid; i < 512; i += 256) {
        int r = i >> 3, q = i & 7;
        uint32_t so = SWZ(r * 128 + q * 16);
        cpa16(sb + MM_G + so, (const uint4*)(g_GpP + ((size_t)b * 64 + r) * 64) + q);
        int half = i >> 8, rest = i & 255, j = rest >> 3, qq = rest & 7;
        uint32_t so2 = half * 4096 + SWZ(j * 128 + qq * 16);
        cpa16(sb + MM_BDH + so2, (const uint4*)(g_basDH + (size_t)j * NN + n0 + half * 64) + qq);
        cpa16(sb + MM_BDL + so2, (const uint4*)(g_basDL + (size_t)j * NN + n0 + half * 64) + qq);
    }
    CPA_COMMIT();
}

// ---------------- fused layer 0-2: conv + synthesis + gelu + DFT --------------
__global__ __launch_bounds__(256, 3)
void mma_layer(int dir, int layer, int rev, const float* __restrict__ cb_all) {
    extern __shared__ char smc[];
    uint32_t sb = smem_u32(smc);
    int tid = threadIdx.x, wid = tid >> 5, lane = tid & 31;
    int b   = rev ? (BB - 1 - (int)blockIdx.y) : (int)blockIdx.y;
    int chk = rev ? (TBC - 1 - (int)blockIdx.x) : (int)blockIdx.x;
    int n0 = chk * NT;

    const bf16* hHsrc = (dir ? g_hH1 : g_hH0) + ((size_t)b * NN + n0) * 64;
    const bf16* hLsrc = (dir ? g_hL1 : g_hL0) + ((size_t)b * NN + n0) * 64;
    bf16* hHdst = (dir ? g_hH0 : g_hH1) + ((size_t)b * NN + n0) * 64;
    bf16* hLdst = (dir ? g_hL0 : g_hL1) + ((size_t)b * NN + n0) * 64;

    layer_loads(sb, tid, layer, b, n0, hHsrc, hLsrc);
    if (tid < 64) ((float*)(smc + MM_CB))[tid] = cb_all[layer * 64 + tid];
    CPA_WAIT(1);
    __syncthreads();

    int wy = wid & 3, wx = wid >> 2;
    float acc[2][4][4];
#pragma unroll
    for (int rt = 0; rt < 2; rt++)
#pragma unroll
        for (int cc = 0; cc < 4; cc++)
#pragma unroll
            for (int k = 0; k < 4; k++) acc[rt][cc][k] = 0.0f;

    layer_gemm(sb, wy, wx, lane, acc);
    __syncthreads();

    int q = lane & 3, g = lane >> 2;
    const float* cbs = (const float*)(smc + MM_CB);
#pragma unroll
    for (int rt = 0; rt < 2; rt++) {
#pragma unroll
        for (int cc = 0; cc < 4; cc++) {
            int o0 = 32 * wx + (cc >> 1) * 16 + (cc & 1) * 8 + 2 * q;
            int r0 = 32 * wy + rt * 16 + g;
            float v0 = gelu_exact(acc[rt][cc][0] + cbs[o0]);
            float v1 = gelu_exact(acc[rt][cc][1] + cbs[o0 + 1]);
            float v2 = gelu_exact(acc[rt][cc][2] + cbs[o0]);
            float v3 = gelu_exact(acc[rt][cc][3] + cbs[o0 + 1]);
            bf16 h0, l0, h1, l1;
            split_bf(v0, h0, l0); split_bf(v1, h1, l1);
            *(uint32_t*)(smc + MM_HH + SWZ(r0 * 128 + o0 * 2)) = pack_bf(h0, h1);
            *(uint32_t*)(smc + MM_HL + SWZ(r0 * 128 + o0 * 2)) = pack_bf(l0, l1);
            split_bf(v2, h0, l0); split_bf(v3, h1, l1);
            *(uint32_t*)(smc + MM_HH + SWZ((r0 + 8) * 128 + o0 * 2)) = pack_bf(h0, h1);
            *(uint32_t*)(smc + MM_HL + SWZ((r0 + 8) * 128 + o0 * 2)) = pack_bf(l0, l1);
        }
    }
    __syncthreads();

    // DFT first; copy-out drains afterwards
    dft_core8(sb, MM_HH, MM_HL, MM_BDH, MM_BDL, wid, lane,
              ((size_t)b * TBC + chk) * J2);

    for (int i = tid; i < 1024; i += 256) {
        int r = i >> 3, qq = i & 7;
        uint32_t so = SWZ(r * 128 + qq * 16);
        ((uint4*)(hHdst + (size_t)r * 64))[qq] = *(uint4*)(smc + MM_HH + so);
        ((uint4*)(hLdst + (size_t)r * 64))[qq] = *(uint4*)(smc + MM_HL + so);
    }
}

// ---------------- fused layer 3 + fc1 + gelu + fc2 ---------------------------
__global__ __launch_bounds__(256, 3)
void mma_layer3fc(const float* __restrict__ cb_all,
                  const float* __restrict__ b1, const float* __restrict__ w2,
                  const float* __restrict__ b2, float* __restrict__ out) {
    extern __shared__ char smc[];
    uint32_t sb = smem_u32(smc);
    int tid = threadIdx.x, wid = tid >> 5, lane = tid & 31;
    int b = blockIdx.y, n0 = blockIdx.x * NT;   // forward (layer 2 ran reversed)

    const bf16* hHsrc = g_hH1 + ((size_t)b * NN + n0) * 64;
    const bf16* hLsrc = g_hL1 + ((size_t)b * NN + n0) * 64;

    layer_loads(sb, tid, 3, b, n0, hHsrc, hLsrc);
    if (tid < 64)  ((float*)(smc + M3_CB))[tid] = cb_all[3 * 64 + tid];
    if (tid < 128) {
        ((float*)(smc + M3_B1))[tid] = b1[tid];
        ((float*)(smc + M3_W2))[tid] = w2[tid];
    }
    CPA_WAIT(1);
    __syncthreads();

    int wy = wid & 3, wx = wid >> 2;
    float acc[2][4][4];
#pragma unroll
    for (int rt = 0; rt < 2; rt++)
#pragma unroll
        for (int cc = 0; cc < 4; cc++)
#pragma unroll
            for (int k = 0; k < 4; k++) acc[rt][cc][k] = 0.0f;

    layer_gemm(sb, wy, wx, lane, acc);
    __syncthreads();   // weight/basis regions now dead

    // prefetch w1 into dead regions [32768, 65536)
    for (int i = tid; i < 2048; i += 256) {
        int buf = i >> 10, rest = i & 1023, r = rest >> 3, q = rest & 7;
        uint32_t so = SWZ(r * 128 + q * 16);
        const bf16* src = buf ? g_w1TL : g_w1TH;
        cpa16(sb + 32768 + buf * 16384 + so, (const uint4*)(src + (size_t)r * 64) + q);
    }
    CPA_COMMIT();

    // epilogue: v = acc + cb (no gelu), split into HH/HL
    int q = lane & 3, g = lane >> 2;
    const float* cbs = (const float*)(smc + M3_CB);
#pragma unroll
    for (int rt = 0; rt < 2; rt++) {
#pragma unroll
        for (int cc = 0; cc < 4; cc++) {
            int o0 = 32 * wx + (cc >> 1) * 16 + (cc & 1) * 8 + 2 * q;
            int r0 = 32 * wy + rt * 16 + g;
            float v0 = acc[rt][cc][0] + cbs[o0];
            float v1 = acc[rt][cc][1] + cbs[o0 + 1];
            float v2 = acc[rt][cc][2] + cbs[o0];
            float v3 = acc[rt][cc][3] + cbs[o0 + 1];
            bf16 h0, l0, h1, l1;
            split_bf(v0, h0, l0); split_bf(v1, h1, l1);
            *(uint32_t*)(smc + MM_HH + SWZ(r0 * 128 + o0 * 2)) = pack_bf(h0, h1);
            *(uint32_t*)(smc + MM_HL + SWZ(r0 * 128 + o0 * 2)) = pack_bf(l0, l1);
            split_bf(v2, h0, l0); split_bf(v3, h1, l1);
            *(uint32_t*)(smc + MM_HH + SWZ((r0 + 8) * 128 + o0 * 2)) = pack_bf(h0, h1);
            *(uint32_t*)(smc + MM_HL + SWZ((r0 + 8) * 128 + o0 * 2)) = pack_bf(l0, l1);
        }
    }
    CPA_WAIT(0);
    __syncthreads();

    // fc1 in two j-halves (register-lean) + gelu·w2 fold (16n x 128j tiling)
    int lr = lane & 7, li = lane >> 3;
    int drA = (li & 1) * 8, dcA = (li >> 1) * 16;
    int drB = (li >> 1) * 8, dcB = (li & 1) * 16;
    int rA0 = 16 * wid;
    const uint32_t W1H = sb + 32768, W1L = sb + 49152;
    const float* b1s = (const float*)(smc + M3_B1);
    const float* w2s = (const float*)(smc + M3_W2);

    float s0 = 0.0f, s1 = 0.0f;
#pragma unroll
    for (int half = 0; half < 2; half++) {
        float fac[8][4];
#pragma unroll
        for (int nt = 0; nt < 8; nt++)
#pragma unroll
            for (int k = 0; k < 4; k++) fac[nt][k] = 0.0f;

#pragma unroll
        for (int s = 0; s < 4; s++) {
            int kb = s * 32;
            uint32_t ah[4], al[4];
            ldsm4(sb + MM_HH + SWZ((rA0 + drA + lr) * 128 + kb + dcA), ah);
            ldsm4(sb + MM_HL + SWZ((rA0 + drA + lr) * 128 + kb + dcA), al);
#pragma unroll
            for (int np = 0; np < 4; np++) {
                int npp = half * 4 + np;
                uint32_t bb[4];
                ldsm4(W1H + SWZ((npp * 16 + drB + lr) * 128 + kb + dcB), bb);
                mma16816(fac[2 * np],     ah, bb);
                mma16816(fac[2 * np + 1], ah, bb + 2);
                mma16816(fac[2 * np],     al, bb);
                mma16816(fac[2 * np + 1], al, bb + 2);
                ldsm4(W1L + SWZ((npp * 16 + drB + lr) * 128 + kb + dcB), bb);
                mma16816(fac[2 * np],     ah, bb);
                mma16816(fac[2 * np + 1], ah, bb + 2);
            }
        }
#pragma unroll
        for (int nt = 0; nt < 8; nt++) {
            int j0 = half * 64 + nt * 8 + 2 * q;
            s0 = fmaf(w2s[j0],     gelu_exact(fac[nt][0] + b1s[j0]),     s0);
            s0 = fmaf(w2s[j0 + 1], gelu_exact(fac[nt][1] + b1s[j0 + 1]), s0);
            s1 = fmaf(w2s[j0],     gelu_exact(fac[nt][2] + b1s[j0]),     s1);
            s1 = fmaf(w2s[j0 + 1], gelu_exact(fac[nt][3] + b1s[j0 + 1]), s1);
        }
    }
    s0 += __shfl_xor_sync(0xffffffffu, s0, 1);
    s0 += __shfl_xor_sync(0xffffffffu, s0, 2);
    s1 += __shfl_xor_sync(0xffffffffu, s1, 1);
    s1 += __shfl_xor_sync(0xffffffffu, s1, 2);
    if (q == 0) {
        float bv = b2[0];
        out[(size_t)b * NN + n0 + 16 * wid + g]     = s0 + bv;
        out[(size_t)b * NN + n0 + 16 * wid + g + 8] = s1 + bv;
    }
}

// ---------------- host launcher ----------------------------------------------
extern "C" void kernel_launch(void* const* d_in, const int* in_sizes, int n_in,
                              void* d_out, int out_size) {
    const float* x    = (const float*)d_in[0];
    const float* t    = (const float*)d_in[1];
    const float* fc0w = (const float*)d_in[2];
    const float* fc0b = (const float*)d_in[3];
    const float* swr  = (const float*)d_in[4];
    const float* swi  = (const float*)d_in[5];
    const float* cw   = (const float*)d_in[6];
    const float* cb   = (const float*)d_in[7];
    const float* w1   = (const float*)d_in[8];
    const float* b1   = (const float*)d_in[9];
    const float* w2   = (const float*)d_in[10];
    const float* b2   = (const float*)d_in[11];
    float* out = (float*)d_out;

    cudaFuncSetAttribute(mma_layer,    cudaFuncAttributeMaxDynamicSharedMemorySize, MM_SZ);
    cudaFuncSetAttribute(mma_layer3fc, cudaFuncAttributeMaxDynamicSharedMemorySize, M3_SZ);
    cudaFuncSetAttribute(fc0dft_kernel, cudaFuncAttributeMaxDynamicSharedMemorySize, F0_SZ);

    dim3 g(TBC, BB);
    dim3 gr(BB, 8);
    prep_all<<<(NN + 4 * 4096 + 128 * 64 + 255) / 256, 256>>>(cw, w1);

    fc0dft_kernel<<<g, 256, F0_SZ>>>(x, t, fc0w, fc0b);      // forward

    const size_t SWL = (size_t)64 * 64 * 16;
    reduce_modemix_kernel<<<BB, 1024>>>(swr + 0 * SWL, swi + 0 * SWL);
    mma_layer<<<g, 256, MM_SZ>>>(0, 0, 1, cb);               // reversed

    reduce_kernel<<<gr, 256>>>();
    modemix_kernel<<<BB, 1024>>>(swr + 1 * SWL, swi + 1 * SWL);
    mma_layer<<<g, 256, MM_SZ>>>(1, 1, 0, cb);               // forward

    reduce_kernel<<<gr, 256>>>();
    modemix_kernel<<<BB, 1024>>>(swr + 2 * SWL, swi + 2 * SWL);
    mma_layer<<<g, 256, MM_SZ>>>(0, 2, 1, cb);               // reversed

    reduce_kernel<<<gr, 256>>>();
    modemix_kernel<<<BB, 1024>>>(swr + 3 * SWL, swi + 3 * SWL);
    mma_layer3fc<<<g, 256, M3_SZ>>>(cb, b1, w2, b2, out);    // forward, fused
}